// round 1
// baseline (speedup 1.0000x reference)
#include <cuda_runtime.h>
#include <cstdint>

#define BATCH   8
#define SEQ     8192
#define BT      65536      // BATCH*SEQ
#define DIM     512
#define HEADS   8
#define HD      64
#define KSLOTS  64
#define SCALE   0.125f     // 1/sqrt(64)
#define EPS_C   1e-20f
#define LN_EPS  1e-5f

// ---------------- scratch (device globals; allocation-free) ----------------
__device__ float d_S[KSLOTS * DIM];          // layernormed slots
__device__ float d_Weff[DIM * DIM];          // Q folded into Wk (pre-scaled)
__device__ float d_beff[DIM];
__device__ float d_L[(size_t)BT * DIM];      // logits -> softmax weights W
__device__ float d_V[(size_t)BT * DIM];      // value projection
__device__ float d_Num[BATCH * DIM * HD];    // [b][(h*64+k)][d]
__device__ float d_C[BATCH * DIM];           // [b][(h*64+k)]

// ---------------- helpers ----------------
__device__ __forceinline__ float blockReduceSum(float v, float* sbuf) {
    #pragma unroll
    for (int o = 16; o > 0; o >>= 1) v += __shfl_down_sync(0xffffffffu, v, o);
    int lane = threadIdx.x & 31, w = threadIdx.x >> 5;
    if (lane == 0) sbuf[w] = v;
    __syncthreads();
    int nw = blockDim.x >> 5;
    v = (threadIdx.x < nw) ? sbuf[threadIdx.x] : 0.f;
    if (w == 0) {
        #pragma unroll
        for (int o = 16; o > 0; o >>= 1) v += __shfl_down_sync(0xffffffffu, v, o);
    }
    if (threadIdx.x == 0) sbuf[0] = v;
    __syncthreads();
    v = sbuf[0];
    __syncthreads();
    return v;
}

// ---------------- 1. layernorm the slots ----------------
__global__ void ln_slots_kernel(const float* __restrict__ slots,
                                const float* __restrict__ g,
                                const float* __restrict__ b) {
    __shared__ float sbuf[32];
    int k = blockIdx.x, tid = threadIdx.x;
    float x = slots[k * DIM + tid];
    float mu = blockReduceSum(x, sbuf) * (1.f / DIM);
    float dv = x - mu;
    float var = blockReduceSum(dv * dv, sbuf) * (1.f / DIM);
    d_S[k * DIM + tid] = dv * rsqrtf(var + LN_EPS) * g[tid] + b[tid];
}

// ---------------- 2. fold Q into Wk: Weff[(h,k),:] = scale * sum_d S[k,h*64+d]*Wk[h*64+d,:]
__global__ void fold_kernel(const float* __restrict__ Wk,
                            const float* __restrict__ bk) {
    int rk = blockIdx.x;                 // (h*64 + k)
    int h = rk >> 6, k = rk & 63;
    __shared__ float sq[HD];
    int tid = threadIdx.x;
    if (tid < HD) sq[tid] = d_S[k * DIM + h * HD + tid];
    __syncthreads();
    for (int j = tid; j < DIM; j += blockDim.x) {
        float acc = 0.f;
        #pragma unroll
        for (int d = 0; d < HD; d++)
            acc = fmaf(sq[d], Wk[(size_t)(h * HD + d) * DIM + j], acc);
        d_Weff[(size_t)rk * DIM + j] = acc * SCALE;
    }
    if (tid == 0) {
        float acc = 0.f;
        #pragma unroll
        for (int d = 0; d < HD; d++) acc += sq[d] * bk[h * HD + d];
        d_beff[rk] = acc * SCALE;
    }
}

// ---------------- 3. NT SGEMM with bias: C[i,j] = sum_k A[i,k]*Bm[j,k] + bias[j]
// M=65536, N=512, K=512. 128x128x16 tiles, 256 threads, 8x8 micro-tile.
#define TBM 128
#define TBN 128
#define TBK 16
__global__ __launch_bounds__(256) void sgemm_nt_bias(const float* __restrict__ A,
                                                     const float* __restrict__ Bm,
                                                     const float* __restrict__ bias,
                                                     float* __restrict__ C) {
    __shared__ float As[TBK][TBM];
    __shared__ float Bs[TBK][TBN];
    const int tid = threadIdx.x;
    const int m0 = blockIdx.y * TBM;
    const int n0 = blockIdx.x * TBN;
    const int tm = tid >> 4, tn = tid & 15;
    float acc[8][8] = {};

    for (int kt = 0; kt < DIM; kt += TBK) {
        #pragma unroll
        for (int l = 0; l < 2; l++) {
            int f = tid + l * 256;
            int r = f >> 2;
            int c = (f & 3) * 4;
            float4 va = *(const float4*)&A[(size_t)(m0 + r) * DIM + kt + c];
            As[c + 0][r] = va.x; As[c + 1][r] = va.y; As[c + 2][r] = va.z; As[c + 3][r] = va.w;
            float4 vb = *(const float4*)&Bm[(size_t)(n0 + r) * DIM + kt + c];
            Bs[c + 0][r] = vb.x; Bs[c + 1][r] = vb.y; Bs[c + 2][r] = vb.z; Bs[c + 3][r] = vb.w;
        }
        __syncthreads();
        #pragma unroll
        for (int kk = 0; kk < TBK; kk++) {
            float a[8], b[8];
            *(float4*)&a[0] = *(const float4*)&As[kk][tm * 8];
            *(float4*)&a[4] = *(const float4*)&As[kk][tm * 8 + 4];
            *(float4*)&b[0] = *(const float4*)&Bs[kk][tn * 8];
            *(float4*)&b[4] = *(const float4*)&Bs[kk][tn * 8 + 4];
            #pragma unroll
            for (int i = 0; i < 8; i++)
                #pragma unroll
                for (int j = 0; j < 8; j++)
                    acc[i][j] = fmaf(a[i], b[j], acc[i][j]);
        }
        __syncthreads();
    }
    #pragma unroll
    for (int i = 0; i < 8; i++) {
        int row = m0 + tm * 8 + i;
        #pragma unroll
        for (int j = 0; j < 8; j += 4) {
            int col = n0 + tn * 8 + j;
            float4 o;
            o.x = acc[i][j + 0] + bias[col + 0];
            o.y = acc[i][j + 1] + bias[col + 1];
            o.z = acc[i][j + 2] + bias[col + 2];
            o.w = acc[i][j + 3] + bias[col + 3];
            *(float4*)&C[(size_t)row * DIM + col] = o;
        }
    }
}

// ---------------- 4. softmax over the 64-slot axis (within each row chunk) ----------------
__global__ void softmax_kernel() {
    int gwarp = (blockIdx.x * blockDim.x + threadIdx.x) >> 5;
    int lane = threadIdx.x & 31;
    size_t row = (size_t)(gwarp >> 3);
    int h = gwarp & 7;
    float* p = d_L + row * DIM + h * HD;
    float x0 = p[lane], x1 = p[lane + 32];
    float m = fmaxf(x0, x1);
    #pragma unroll
    for (int o = 16; o > 0; o >>= 1) m = fmaxf(m, __shfl_xor_sync(0xffffffffu, m, o));
    float e0 = expf(x0 - m), e1 = expf(x1 - m);
    float s = e0 + e1;
    #pragma unroll
    for (int o = 16; o > 0; o >>= 1) s += __shfl_xor_sync(0xffffffffu, s, o);
    float inv = 1.f / s;
    p[lane] = e0 * inv;
    p[lane + 32] = e1 * inv;
}

// ---------------- 5. zero accumulators ----------------
__global__ void zero_kernel() {
    int i = blockIdx.x * blockDim.x + threadIdx.x;
    if (i < BATCH * DIM * HD) d_Num[i] = 0.f;
    if (i < BATCH * DIM)      d_C[i] = 0.f;
}

// ---------------- 6. Num[b,(h,k),d] = sum_s W[b,s,(h,k)] * V[b,s,(h,d)]; C = sum_s W
#define SCH 1024
__global__ __launch_bounds__(256) void accum_kernel() {
    int sc = blockIdx.x, h = blockIdx.y, b = blockIdx.z;
    __shared__ float Ws[32][64];
    __shared__ float Vs[32][64];
    int tid = threadIdx.x;
    int tk = (tid >> 4) * 4, td = (tid & 15) * 4;
    float acc[4][4] = {};
    float cs = 0.f;
    size_t base = ((size_t)b * SEQ + (size_t)sc * SCH) * DIM + h * HD;
    for (int st = 0; st < SCH; st += 32) {
        #pragma unroll
        for (int l = 0; l < 2; l++) {
            int f = tid + l * 256;
            int r = f >> 4;
            int c = (f & 15) * 4;
            *(float4*)&Ws[r][c] = *(const float4*)&d_L[base + (size_t)(st + r) * DIM + c];
            *(float4*)&Vs[r][c] = *(const float4*)&d_V[base + (size_t)(st + r) * DIM + c];
        }
        __syncthreads();
        #pragma unroll 8
        for (int r = 0; r < 32; r++) {
            float wv[4], vv[4];
            *(float4*)&wv[0] = *(const float4*)&Ws[r][tk];
            *(float4*)&vv[0] = *(const float4*)&Vs[r][td];
            #pragma unroll
            for (int i = 0; i < 4; i++)
                #pragma unroll
                for (int j = 0; j < 4; j++)
                    acc[i][j] = fmaf(wv[i], vv[j], acc[i][j]);
        }
        if (tid < 64) {
            #pragma unroll
            for (int r = 0; r < 32; r++) cs += Ws[r][tid];
        }
        __syncthreads();
    }
    #pragma unroll
    for (int i = 0; i < 4; i++)
        #pragma unroll
        for (int j = 0; j < 4; j++)
            atomicAdd(&d_Num[((size_t)b * DIM + h * HD + tk + i) * HD + td + j], acc[i][j]);
    if (tid < 64) atomicAdd(&d_C[b * DIM + h * HD + tid], cs);
}

// ---------------- 7. divide by C, transpose heads back, final layernorm ----------------
__global__ void final_kernel(const float* __restrict__ g,
                             const float* __restrict__ bb,
                             float* __restrict__ out) {
    __shared__ float sbuf[32];
    int blk = blockIdx.x;              // b*64 + k
    int b = blk >> 6, k = blk & 63;
    int tid = threadIdx.x;             // = h*64 + d
    int h = tid >> 6, d = tid & 63;
    float c = d_C[b * DIM + h * HD + k];
    float v = d_Num[((size_t)b * DIM + h * HD + k) * HD + d] / (c + EPS_C);
    float mu = blockReduceSum(v, sbuf) * (1.f / DIM);
    float dv = v - mu;
    float var = blockReduceSum(dv * dv, sbuf) * (1.f / DIM);
    out[(size_t)blk * DIM + tid] = dv * rsqrtf(var + LN_EPS) * g[tid] + bb[tid];
}

// ---------------- launch ----------------
extern "C" void kernel_launch(void* const* d_in, const int* in_sizes, int n_in,
                              void* d_out, int out_size) {
    const float* X       = (const float*)d_in[0];
    const float* slots_w = (const float*)d_in[1];
    const float* g_slots = (const float*)d_in[2];
    const float* b_slots = (const float*)d_in[3];
    const float* Wk      = (const float*)d_in[4];
    const float* bk      = (const float*)d_in[5];
    const float* Wv      = (const float*)d_in[6];
    const float* bv      = (const float*)d_in[7];
    const float* g_after = (const float*)d_in[8];
    const float* b_after = (const float*)d_in[9];
    float* out = (float*)d_out;

    float *pWeff, *pbeff, *pL, *pV;
    cudaGetSymbolAddress((void**)&pWeff, d_Weff);
    cudaGetSymbolAddress((void**)&pbeff, d_beff);
    cudaGetSymbolAddress((void**)&pL, d_L);
    cudaGetSymbolAddress((void**)&pV, d_V);

    ln_slots_kernel<<<KSLOTS, DIM>>>(slots_w, g_slots, b_slots);
    fold_kernel<<<DIM, 256>>>(Wk, bk);

    dim3 ggrid(DIM / TBN, BT / TBM);   // (4, 512)
    sgemm_nt_bias<<<ggrid, 256>>>(X, pWeff, pbeff, pL);
    sgemm_nt_bias<<<ggrid, 256>>>(X, Wv, bv, pV);

    softmax_kernel<<<BT * HEADS / 8, 256>>>();
    zero_kernel<<<(BATCH * DIM * HD + 255) / 256, 256>>>();
    accum_kernel<<<dim3(SEQ / SCH, HEADS, BATCH), 256>>>();
    final_kernel<<<BATCH * KSLOTS, DIM>>>(g_after, b_after, out);
}

// round 3
// speedup vs baseline: 2.6261x; 2.6261x over previous
#include <cuda_runtime.h>
#include <cstdint>

#define BATCH   8
#define SEQ     8192
#define BT      65536
#define DIM     512
#define HEADS   8
#define HD      64
#define KSLOTS  64
#define SCALE   0.125f
#define EPS_C   1e-20f
#define LN_EPS  1e-5f

#define NTOT    1024        // [logits(512) | V(512)]
#define MT      128
#define NT      256
#define KC      32          // k-chunk
#define NCHUNK  16          // 512/32

// ---------------- scratch ----------------
__device__ float d_S[KSLOTS * DIM];
__device__ float d_Weff[DIM * DIM];
__device__ float d_beff[DIM];
__device__ float d_bcat[NTOT];
__device__ float d_Xr[(size_t)BT * DIM];       // tf32-rounded X
__device__ float d_Wall[(size_t)NTOT * DIM];   // tf32-rounded [Weff; Wv]
__device__ float d_LV[(size_t)BT * NTOT];
__device__ float d_Num[BATCH * DIM * HD];
__device__ float d_C[BATCH * DIM];

// ---------------- helpers ----------------
__device__ __forceinline__ uint32_t s2u(const void* p) {
    uint32_t a;
    asm("{ .reg .u64 t; cvta.to.shared.u64 t, %1; cvt.u32.u64 %0, t; }" : "=r"(a) : "l"(p));
    return a;
}
__device__ __forceinline__ float tf32r(float x) {
    uint32_t u;
    asm("cvt.rna.tf32.f32 %0, %1;" : "=r"(u) : "f"(x));
    return __uint_as_float(u);
}
// swizzled float index within a [rows][32] tile
#define SIDX(r, c) (((r) << 5) + ((c) ^ (((r) & 7) << 2)))

__device__ __forceinline__ float blockReduceSum(float v, float* sbuf) {
    #pragma unroll
    for (int o = 16; o > 0; o >>= 1) v += __shfl_down_sync(0xffffffffu, v, o);
    int lane = threadIdx.x & 31, w = threadIdx.x >> 5;
    if (lane == 0) sbuf[w] = v;
    __syncthreads();
    int nw = blockDim.x >> 5;
    v = (threadIdx.x < nw) ? sbuf[threadIdx.x] : 0.f;
    if (w == 0) {
        #pragma unroll
        for (int o = 16; o > 0; o >>= 1) v += __shfl_down_sync(0xffffffffu, v, o);
    }
    if (threadIdx.x == 0) sbuf[0] = v;
    __syncthreads();
    v = sbuf[0];
    __syncthreads();
    return v;
}

// ---------------- 1. layernorm slots ----------------
__global__ void ln_slots_kernel(const float* __restrict__ slots,
                                const float* __restrict__ g,
                                const float* __restrict__ b) {
    __shared__ float sbuf[32];
    int k = blockIdx.x, tid = threadIdx.x;
    float x = slots[k * DIM + tid];
    float mu = blockReduceSum(x, sbuf) * (1.f / DIM);
    float dv = x - mu;
    float var = blockReduceSum(dv * dv, sbuf) * (1.f / DIM);
    d_S[k * DIM + tid] = dv * rsqrtf(var + LN_EPS) * g[tid] + b[tid];
}

// ---------------- 2. fold Q into Wk ----------------
__global__ void fold_kernel(const float* __restrict__ Wk,
                            const float* __restrict__ bk) {
    int rk = blockIdx.x;
    int h = rk >> 6, k = rk & 63;
    __shared__ float sq[HD];
    int tid = threadIdx.x;
    if (tid < HD) sq[tid] = d_S[k * DIM + h * HD + tid];
    __syncthreads();
    for (int j = tid; j < DIM; j += blockDim.x) {
        float acc = 0.f;
        #pragma unroll
        for (int d = 0; d < HD; d++)
            acc = fmaf(sq[d], Wk[(size_t)(h * HD + d) * DIM + j], acc);
        d_Weff[(size_t)rk * DIM + j] = acc * SCALE;
    }
    if (tid == 0) {
        float acc = 0.f;
        #pragma unroll
        for (int d = 0; d < HD; d++) acc += sq[d] * bk[h * HD + d];
        d_beff[rk] = acc * SCALE;
    }
}

// ---------------- 3. tf32 rounding passes ----------------
__global__ void convx_kernel(const float* __restrict__ X) {
    size_t idx = (size_t)blockIdx.x * 256 + threadIdx.x;   // BT*128 float4s
    float4 x = *(const float4*)&X[idx * 4];
    float4 o = {tf32r(x.x), tf32r(x.y), tf32r(x.z), tf32r(x.w)};
    *(float4*)&d_Xr[idx * 4] = o;
}

__global__ void convw_kernel(const float* __restrict__ Wv) {
    size_t idx = (size_t)blockIdx.x * 256 + threadIdx.x;   // 1024*128 float4s
    int row = (int)(idx >> 7);
    int c4 = ((int)idx & 127) << 2;
    const float* src = (row < 512) ? &d_Weff[(size_t)row * DIM + c4]
                                   : &Wv[(size_t)(row - 512) * DIM + c4];
    float4 x = *(const float4*)src;
    float4 o = {tf32r(x.x), tf32r(x.y), tf32r(x.z), tf32r(x.w)};
    *(float4*)&d_Wall[(size_t)row * DIM + c4] = o;
}

__global__ void bcat_kernel(const float* __restrict__ bv) {
    int i = blockIdx.x * 256 + threadIdx.x;
    if (i < NTOT) d_bcat[i] = (i < 512) ? d_beff[i] : bv[i - 512];
}

// ---------------- 4. tf32 mma.sync GEMM + fused softmax ----------------
// smem floats: A stages: s*4096 (3x 16KB); B stages: 12288 + s*8192 (3x 32KB);
// bias @36864 (256 floats). Epilogue reuses [0, 16896) as 128x132 tile.
#define SMEMF_A(s)   ((s) * 4096)
#define SMEMF_B(s)   (12288 + (s) * 8192)
#define SMEMF_BIAS   36864
#define SMEM_BYTES   ((36864 + 256) * 4)

__device__ __forceinline__ void load_chunk(uint32_t sb, const float* __restrict__ Xr,
                                           const float* __restrict__ Wall,
                                           int c, int s, int m0, int n0, int tid) {
    int kt = c * KC;
    uint32_t abase = sb + SMEMF_A(s) * 4;
    uint32_t bbase = sb + SMEMF_B(s) * 4;
    // A: 128 rows x 8 float4 = 1024 tasks
    #pragma unroll
    for (int l = 0; l < 2; l++) {
        int t = tid + l * 512;
        int r = t >> 3, cc = (t & 7) * 4;
        uint32_t dst = abase + SIDX(r, cc) * 4;
        const float* src = Xr + (size_t)(m0 + r) * DIM + kt + cc;
        asm volatile("cp.async.cg.shared.global [%0], [%1], 16;" :: "r"(dst), "l"(src));
    }
    // B: 256 rows x 8 float4 = 2048 tasks
    #pragma unroll
    for (int l = 0; l < 4; l++) {
        int t = tid + l * 512;
        int r = t >> 3, cc = (t & 7) * 4;
        uint32_t dst = bbase + SIDX(r, cc) * 4;
        const float* src = Wall + (size_t)(n0 + r) * DIM + kt + cc;
        asm volatile("cp.async.cg.shared.global [%0], [%1], 16;" :: "r"(dst), "l"(src));
    }
    asm volatile("cp.async.commit_group;" ::: "memory");
}

__global__ void __launch_bounds__(512) gemm_tf32(const float* __restrict__ Xr,
                                                 const float* __restrict__ Wall,
                                                 const float* __restrict__ bias,
                                                 float* __restrict__ out) {
    extern __shared__ float smf[];
    uint32_t sb = s2u(smf);
    const int tid = threadIdx.x;
    const int wid = tid >> 5, lane = tid & 31;
    const int g = lane >> 2, tg = lane & 3;
    const int wm = (wid & 3) * 32;            // warp M offset (4 warps x 32)
    const int wn = (wid >> 2) * 64;           // warp N offset (4 groups x 64)
    const int m0 = blockIdx.y * MT;
    const int n0 = blockIdx.x * NT;

    if (tid < NT) smf[SMEMF_BIAS + tid] = bias[n0 + tid];

    float d[2][8][4];
    #pragma unroll
    for (int mt = 0; mt < 2; mt++)
        #pragma unroll
        for (int nt = 0; nt < 8; nt++)
            #pragma unroll
            for (int i = 0; i < 4; i++) d[mt][nt][i] = 0.f;

    load_chunk(sb, Xr, Wall, 0, 0, m0, n0, tid);
    load_chunk(sb, Xr, Wall, 1, 1, m0, n0, tid);

    for (int c = 0; c < NCHUNK; c++) {
        int s = c % 3;
        if (c + 2 < NCHUNK) load_chunk(sb, Xr, Wall, c + 2, (c + 2) % 3, m0, n0, tid);
        if (c <= NCHUNK - 3)      asm volatile("cp.async.wait_group 2;" ::: "memory");
        else if (c == NCHUNK - 2) asm volatile("cp.async.wait_group 1;" ::: "memory");
        else                      asm volatile("cp.async.wait_group 0;" ::: "memory");
        __syncthreads();

        const float* As = smf + SMEMF_A(s);
        const float* Bs = smf + SMEMF_B(s);
        #pragma unroll
        for (int ks = 0; ks < 4; ks++) {
            int kb = ks * 8;
            uint32_t a[2][4], b[8][2];
            #pragma unroll
            for (int mt = 0; mt < 2; mt++) {
                int r = wm + mt * 16 + g;
                a[mt][0] = __float_as_uint(As[SIDX(r,     kb + tg)]);
                a[mt][1] = __float_as_uint(As[SIDX(r + 8, kb + tg)]);
                a[mt][2] = __float_as_uint(As[SIDX(r,     kb + tg + 4)]);
                a[mt][3] = __float_as_uint(As[SIDX(r + 8, kb + tg + 4)]);
            }
            #pragma unroll
            for (int nt = 0; nt < 8; nt++) {
                int n = wn + nt * 8 + g;
                b[nt][0] = __float_as_uint(Bs[SIDX(n, kb + tg)]);
                b[nt][1] = __float_as_uint(Bs[SIDX(n, kb + tg + 4)]);
            }
            #pragma unroll
            for (int mt = 0; mt < 2; mt++)
                #pragma unroll
                for (int nt = 0; nt < 8; nt++)
                    asm volatile(
                        "mma.sync.aligned.m16n8k8.row.col.f32.tf32.tf32.f32 "
                        "{%0,%1,%2,%3}, {%4,%5,%6,%7}, {%8,%9}, {%0,%1,%2,%3};"
                        : "+f"(d[mt][nt][0]), "+f"(d[mt][nt][1]),
                          "+f"(d[mt][nt][2]), "+f"(d[mt][nt][3])
                        : "r"(a[mt][0]), "r"(a[mt][1]), "r"(a[mt][2]), "r"(a[mt][3]),
                          "r"(b[nt][0]), "r"(b[nt][1]));
        }
        __syncthreads();
    }

    // ---------------- epilogue: bias + (softmax for logits) via smem halves
    const bool is_logits = (blockIdx.x < 2);
    const int wn_local = ((wid >> 2) & 1) * 64;
    #pragma unroll 1
    for (int h = 0; h < 2; h++) {
        __syncthreads();
        if ((wid >> 3) == h) {
            #pragma unroll
            for (int mt = 0; mt < 2; mt++) {
                int r = wm + mt * 16 + g;
                #pragma unroll
                for (int nt = 0; nt < 8; nt++) {
                    int cl = wn_local + nt * 8 + tg * 2;
                    float b0 = smf[SMEMF_BIAS + h * 128 + cl];
                    float b1 = smf[SMEMF_BIAS + h * 128 + cl + 1];
                    float2 v0 = {d[mt][nt][0] + b0, d[mt][nt][1] + b1};
                    float2 v1 = {d[mt][nt][2] + b0, d[mt][nt][3] + b1};
                    *(float2*)&smf[r * 132 + cl]       = v0;
                    *(float2*)&smf[(r + 8) * 132 + cl] = v1;
                }
            }
        }
        __syncthreads();
        if (is_logits) {
            if (tid < 256) {
                int r = tid >> 1, hg = tid & 1;
                const float* row = smf + r * 132 + hg * 64;
                float v[64];
                float m = row[0];
                #pragma unroll
                for (int i = 0; i < 64; i++) { v[i] = row[i]; m = fmaxf(m, v[i]); }
                float ssum = 0.f;
                #pragma unroll
                for (int i = 0; i < 64; i++) { v[i] = expf(v[i] - m); ssum += v[i]; }
                float inv = 1.f / ssum;
                float* op = out + (size_t)(m0 + r) * NTOT + n0 + h * 128 + hg * 64;
                #pragma unroll
                for (int i = 0; i < 64; i += 4) {
                    float4 o = {v[i] * inv, v[i+1] * inv, v[i+2] * inv, v[i+3] * inv};
                    *(float4*)(op + i) = o;
                }
            }
        } else {
            for (int i = tid; i < 128 * 32; i += 512) {
                int r = i >> 5, c4 = (i & 31) * 4;
                float4 val = *(const float4*)&smf[r * 132 + c4];
                *(float4*)&out[(size_t)(m0 + r) * NTOT + n0 + h * 128 + c4] = val;
            }
        }
    }
}

// ---------------- 5. zero accumulators ----------------
__global__ void zero_kernel() {
    int i = blockIdx.x * blockDim.x + threadIdx.x;
    if (i < BATCH * DIM * HD) d_Num[i] = 0.f;
    if (i < BATCH * DIM)      d_C[i] = 0.f;
}

// ---------------- 6. Num = sum_s W*V, C = sum_s W ----------------
#define SCH 1024
__global__ __launch_bounds__(256) void accum_kernel() {
    int sc = blockIdx.x, h = blockIdx.y, b = blockIdx.z;
    __shared__ float Ws[32][64];
    __shared__ float Vs[32][64];
    int tid = threadIdx.x;
    int tk = (tid >> 4) * 4, td = (tid & 15) * 4;
    float acc[4][4] = {};
    float cs = 0.f;
    size_t base = ((size_t)b * SEQ + (size_t)sc * SCH) * NTOT + h * HD;
    for (int st = 0; st < SCH; st += 32) {
        #pragma unroll
        for (int l = 0; l < 2; l++) {
            int f = tid + l * 256;
            int r = f >> 4;
            int c = (f & 15) * 4;
            *(float4*)&Ws[r][c] = *(const float4*)&d_LV[base + (size_t)(st + r) * NTOT + c];
            *(float4*)&Vs[r][c] = *(const float4*)&d_LV[base + 512 + (size_t)(st + r) * NTOT + c];
        }
        __syncthreads();
        #pragma unroll 8
        for (int r = 0; r < 32; r++) {
            float wv[4], vv[4];
            *(float4*)&wv[0] = *(const float4*)&Ws[r][tk];
            *(float4*)&vv[0] = *(const float4*)&Vs[r][td];
            #pragma unroll
            for (int i = 0; i < 4; i++)
                #pragma unroll
                for (int j = 0; j < 4; j++)
                    acc[i][j] = fmaf(wv[i], vv[j], acc[i][j]);
        }
        if (tid < 64) {
            #pragma unroll
            for (int r = 0; r < 32; r++) cs += Ws[r][tid];
        }
        __syncthreads();
    }
    #pragma unroll
    for (int i = 0; i < 4; i++)
        #pragma unroll
        for (int j = 0; j < 4; j++)
            atomicAdd(&d_Num[((size_t)b * DIM + h * HD + tk + i) * HD + td + j], acc[i][j]);
    if (tid < 64) atomicAdd(&d_C[b * DIM + h * HD + tid], cs);
}

// ---------------- 7. divide, transpose, final LN ----------------
__global__ void final_kernel(const float* __restrict__ g,
                             const float* __restrict__ bb,
                             float* __restrict__ out) {
    __shared__ float sbuf[32];
    int blk = blockIdx.x;
    int b = blk >> 6, k = blk & 63;
    int tid = threadIdx.x;
    int h = tid >> 6, d = tid & 63;
    float c = d_C[b * DIM + h * HD + k];
    float v = d_Num[((size_t)b * DIM + h * HD + k) * HD + d] / (c + EPS_C);
    float mu = blockReduceSum(v, sbuf) * (1.f / DIM);
    float dv = v - mu;
    float var = blockReduceSum(dv * dv, sbuf) * (1.f / DIM);
    out[(size_t)blk * DIM + tid] = dv * rsqrtf(var + LN_EPS) * g[tid] + bb[tid];
}

// ---------------- launch ----------------
extern "C" void kernel_launch(void* const* d_in, const int* in_sizes, int n_in,
                              void* d_out, int out_size) {
    const float* X       = (const float*)d_in[0];
    const float* slots_w = (const float*)d_in[1];
    const float* g_slots = (const float*)d_in[2];
    const float* b_slots = (const float*)d_in[3];
    const float* Wk      = (const float*)d_in[4];
    const float* bk      = (const float*)d_in[5];
    const float* Wv      = (const float*)d_in[6];
    const float* bv      = (const float*)d_in[7];
    const float* g_after = (const float*)d_in[8];
    const float* b_after = (const float*)d_in[9];
    float* out = (float*)d_out;

    float *pXr, *pWall, *pbcat, *pLV;
    cudaGetSymbolAddress((void**)&pXr, d_Xr);
    cudaGetSymbolAddress((void**)&pWall, d_Wall);
    cudaGetSymbolAddress((void**)&pbcat, d_bcat);
    cudaGetSymbolAddress((void**)&pLV, d_LV);

    static bool attr_set = false;
    if (!attr_set) {
        cudaFuncSetAttribute(gemm_tf32, cudaFuncAttributeMaxDynamicSharedMemorySize, SMEM_BYTES);
        attr_set = true;
    }

    ln_slots_kernel<<<KSLOTS, DIM>>>(slots_w, g_slots, b_slots);
    fold_kernel<<<DIM, 256>>>(Wk, bk);
    convw_kernel<<<512, 256>>>(Wv);
    bcat_kernel<<<4, 256>>>(bv);
    convx_kernel<<<32768, 256>>>(X);

    dim3 ggrid(NTOT / NT, BT / MT);   // (4, 512)
    gemm_tf32<<<ggrid, 512, SMEM_BYTES>>>(pXr, pWall, pbcat, pLV);

    zero_kernel<<<(BATCH * DIM * HD + 255) / 256, 256>>>();
    accum_kernel<<<dim3(SEQ / SCH, HEADS, BATCH), 256>>>();
    final_kernel<<<BATCH * KSLOTS, DIM>>>(g_after, b_after, out);
}

// round 6
// speedup vs baseline: 3.4814x; 1.3257x over previous
#include <cuda_runtime.h>
#include <cuda_fp16.h>
#include <cstdint>

#define BATCH   8
#define SEQ     8192
#define BT      65536
#define DIM     512
#define HEADS   8
#define HD      64
#define KSLOTS  64
#define SCALE   0.125f
#define EPS_C   1e-20f
#define LN_EPS  1e-5f

#define NTOT    1024        // [logits(512) | V(512)]
#define MT      128
#define NT      256
#define KC      64          // k-chunk (halves)
#define NCHUNK  8           // 512/64

// ---------------- scratch ----------------
__device__ float d_S[KSLOTS * DIM];
__device__ float d_Weff[DIM * DIM];
__device__ float d_beff[DIM];
__device__ float d_bcat[NTOT];
__device__ __half d_Xh[(size_t)BT * DIM];
__device__ __half d_Wh[(size_t)NTOT * DIM];
__device__ float d_LV[(size_t)BT * NTOT];
__device__ float d_Num[BATCH * DIM * HD];
__device__ float d_C[BATCH * DIM];

// ---------------- helpers ----------------
__device__ __forceinline__ uint32_t s2u(const void* p) {
    uint32_t a;
    asm("{ .reg .u64 t; cvta.to.shared.u64 t, %1; cvt.u32.u64 %0, t; }" : "=r"(a) : "l"(p));
    return a;
}
// swizzled dword index within a [rows][32-dword] tile
#define SIDX(r, c) (((r) << 5) + ((c) ^ (((r) & 7) << 2)))

__device__ __forceinline__ float blockReduceSum(float v, float* sbuf) {
    #pragma unroll
    for (int o = 16; o > 0; o >>= 1) v += __shfl_down_sync(0xffffffffu, v, o);
    int lane = threadIdx.x & 31, w = threadIdx.x >> 5;
    if (lane == 0) sbuf[w] = v;
    __syncthreads();
    int nw = blockDim.x >> 5;
    v = (threadIdx.x < nw) ? sbuf[threadIdx.x] : 0.f;
    if (w == 0) {
        #pragma unroll
        for (int o = 16; o > 0; o >>= 1) v += __shfl_down_sync(0xffffffffu, v, o);
    }
    if (threadIdx.x == 0) sbuf[0] = v;
    __syncthreads();
    v = sbuf[0];
    __syncthreads();
    return v;
}

// ---------------- 1. layernorm slots ----------------
__global__ void ln_slots_kernel(const float* __restrict__ slots,
                                const float* __restrict__ g,
                                const float* __restrict__ b) {
    __shared__ float sbuf[32];
    int k = blockIdx.x, tid = threadIdx.x;
    float x = slots[k * DIM + tid];
    float mu = blockReduceSum(x, sbuf) * (1.f / DIM);
    float dv = x - mu;
    float var = blockReduceSum(dv * dv, sbuf) * (1.f / DIM);
    d_S[k * DIM + tid] = dv * rsqrtf(var + LN_EPS) * g[tid] + b[tid];
}

// ---------------- 2. fold Q into Wk ----------------
__global__ void fold_kernel(const float* __restrict__ Wk,
                            const float* __restrict__ bk) {
    int rk = blockIdx.x;
    int h = rk >> 6, k = rk & 63;
    __shared__ float sq[HD];
    int tid = threadIdx.x;
    if (tid < HD) sq[tid] = d_S[k * DIM + h * HD + tid];
    __syncthreads();
    for (int j = tid; j < DIM; j += blockDim.x) {
        float acc = 0.f;
        #pragma unroll
        for (int d = 0; d < HD; d++)
            acc = fmaf(sq[d], Wk[(size_t)(h * HD + d) * DIM + j], acc);
        d_Weff[(size_t)rk * DIM + j] = acc * SCALE;
    }
    if (tid == 0) {
        float acc = 0.f;
        #pragma unroll
        for (int d = 0; d < HD; d++) acc += sq[d] * bk[h * HD + d];
        d_beff[rk] = acc * SCALE;
    }
}

// ---------------- 3. fp32 -> fp16 conversions ----------------
__device__ __forceinline__ uint4 pack8(float4 a, float4 b) {
    __half2 p0 = __floats2half2_rn(a.x, a.y);
    __half2 p1 = __floats2half2_rn(a.z, a.w);
    __half2 p2 = __floats2half2_rn(b.x, b.y);
    __half2 p3 = __floats2half2_rn(b.z, b.w);
    uint4 o;
    o.x = *(uint32_t*)&p0; o.y = *(uint32_t*)&p1;
    o.z = *(uint32_t*)&p2; o.w = *(uint32_t*)&p3;
    return o;
}

__global__ void convx_kernel(const float* __restrict__ X) {
    size_t idx = (size_t)blockIdx.x * 256 + threadIdx.x;   // BT*DIM/8
    size_t base = idx * 8;
    float4 a = *(const float4*)&X[base];
    float4 b = *(const float4*)&X[base + 4];
    *(uint4*)&d_Xh[base] = pack8(a, b);
}

__global__ void convw_kernel(const float* __restrict__ Wv,
                             const float* __restrict__ bv) {
    size_t idx = (size_t)blockIdx.x * 256 + threadIdx.x;   // 1024*512/8 = 65536
    int row = (int)(idx >> 6);
    int c8 = ((int)idx & 63) << 3;
    const float* src = (row < 512) ? &d_Weff[(size_t)row * DIM + c8]
                                   : &Wv[(size_t)(row - 512) * DIM + c8];
    float4 a = *(const float4*)src;
    float4 b = *(const float4*)(src + 4);
    *(uint4*)&d_Wh[(size_t)row * DIM + c8] = pack8(a, b);
    if (c8 == 0) d_bcat[row] = (row < 512) ? d_beff[row] : bv[row - 512];
}

// ---------------- 4. fp16 mma.sync GEMM + fused softmax ----------------
// smem dwords: A stages s*4096 (3x16KB); B stages 12288+s*8192 (3x32KB);
// bias @36864 (256 floats). Epilogue reuses [0, 128*132) floats.
#define SMD_A(s)     ((s) * 4096)
#define SMD_B(s)     (12288 + (s) * 8192)
#define SMD_BIAS     36864
#define SMEM_BYTES   ((36864 + 256) * 4)

__device__ __forceinline__ void load_chunk(uint32_t sb, const __half* __restrict__ Xh,
                                           const __half* __restrict__ Wh,
                                           int c, int s, int m0, int n0, int tid) {
    int kt = c * KC;
    uint32_t abase = sb + SMD_A(s) * 4;
    uint32_t bbase = sb + SMD_B(s) * 4;
    // A: 128 rows x 8 16B-chunks
    #pragma unroll
    for (int l = 0; l < 2; l++) {
        int t = tid + l * 512;
        int r = t >> 3, c8 = t & 7;
        uint32_t dst = abase + SIDX(r, c8 * 4) * 4;
        const __half* src = Xh + (size_t)(m0 + r) * DIM + kt + c8 * 8;
        asm volatile("cp.async.cg.shared.global [%0], [%1], 16;" :: "r"(dst), "l"(src));
    }
    // B: 256 rows x 8 16B-chunks
    #pragma unroll
    for (int l = 0; l < 4; l++) {
        int t = tid + l * 512;
        int r = t >> 3, c8 = t & 7;
        uint32_t dst = bbase + SIDX(r, c8 * 4) * 4;
        const __half* src = Wh + (size_t)(n0 + r) * DIM + kt + c8 * 8;
        asm volatile("cp.async.cg.shared.global [%0], [%1], 16;" :: "r"(dst), "l"(src));
    }
    asm volatile("cp.async.commit_group;" ::: "memory");
}

__global__ void __launch_bounds__(512) gemm_fp16(const __half* __restrict__ Xh,
                                                 const __half* __restrict__ Wh,
                                                 const float* __restrict__ bias,
                                                 float* __restrict__ out) {
    extern __shared__ uint32_t sm32[];
    float* smf = (float*)sm32;
    uint32_t sb = s2u(sm32);
    const int tid = threadIdx.x;
    const int wid = tid >> 5, lane = tid & 31;
    const int g = lane >> 2, tg = lane & 3;
    const int wm = (wid & 3) * 32;
    const int wn = (wid >> 2) * 64;
    const int m0 = blockIdx.y * MT;
    const int n0 = blockIdx.x * NT;

    if (tid < NT) smf[SMD_BIAS + tid] = bias[n0 + tid];

    float d[2][8][4];
    #pragma unroll
    for (int mt = 0; mt < 2; mt++)
        #pragma unroll
        for (int nt = 0; nt < 8; nt++)
            #pragma unroll
            for (int i = 0; i < 4; i++) d[mt][nt][i] = 0.f;

    load_chunk(sb, Xh, Wh, 0, 0, m0, n0, tid);
    load_chunk(sb, Xh, Wh, 1, 1, m0, n0, tid);

    for (int c = 0; c < NCHUNK; c++) {
        int s = c % 3;
        if (c + 2 < NCHUNK) load_chunk(sb, Xh, Wh, c + 2, (c + 2) % 3, m0, n0, tid);
        if (c <= NCHUNK - 3)      asm volatile("cp.async.wait_group 2;" ::: "memory");
        else if (c == NCHUNK - 2) asm volatile("cp.async.wait_group 1;" ::: "memory");
        else                      asm volatile("cp.async.wait_group 0;" ::: "memory");
        __syncthreads();

        const uint32_t* As = sm32 + SMD_A(s);
        const uint32_t* Bs = sm32 + SMD_B(s);
        #pragma unroll
        for (int ks = 0; ks < 4; ks++) {
            int kd = ks * 8;
            uint32_t a[2][4], b[8][2];
            #pragma unroll
            for (int mt = 0; mt < 2; mt++) {
                int r = wm + mt * 16 + g;
                a[mt][0] = As[SIDX(r,     kd + tg)];
                a[mt][1] = As[SIDX(r + 8, kd + tg)];
                a[mt][2] = As[SIDX(r,     kd + tg + 4)];
                a[mt][3] = As[SIDX(r + 8, kd + tg + 4)];
            }
            #pragma unroll
            for (int nt = 0; nt < 8; nt++) {
                int n = wn + nt * 8 + g;
                b[nt][0] = Bs[SIDX(n, kd + tg)];
                b[nt][1] = Bs[SIDX(n, kd + tg + 4)];
            }
            #pragma unroll
            for (int mt = 0; mt < 2; mt++)
                #pragma unroll
                for (int nt = 0; nt < 8; nt++)
                    asm volatile(
                        "mma.sync.aligned.m16n8k16.row.col.f32.f16.f16.f32 "
                        "{%0,%1,%2,%3}, {%4,%5,%6,%7}, {%8,%9}, {%0,%1,%2,%3};"
                        : "+f"(d[mt][nt][0]), "+f"(d[mt][nt][1]),
                          "+f"(d[mt][nt][2]), "+f"(d[mt][nt][3])
                        : "r"(a[mt][0]), "r"(a[mt][1]), "r"(a[mt][2]), "r"(a[mt][3]),
                          "r"(b[nt][0]), "r"(b[nt][1]));
        }
        __syncthreads();
    }

    // ---------------- epilogue: bias + (softmax for logits) via smem halves
    const bool is_logits = (blockIdx.x < 2);
    const int wn_local = ((wid >> 2) & 1) * 64;
    #pragma unroll 1
    for (int h = 0; h < 2; h++) {
        __syncthreads();
        if ((wid >> 3) == h) {
            #pragma unroll
            for (int mt = 0; mt < 2; mt++) {
                int r = wm + mt * 16 + g;
                #pragma unroll
                for (int nt = 0; nt < 8; nt++) {
                    int cl = wn_local + nt * 8 + tg * 2;
                    float b0 = smf[SMD_BIAS + h * 128 + cl];
                    float b1 = smf[SMD_BIAS + h * 128 + cl + 1];
                    float2 v0 = {d[mt][nt][0] + b0, d[mt][nt][1] + b1};
                    float2 v1 = {d[mt][nt][2] + b0, d[mt][nt][3] + b1};
                    *(float2*)&smf[r * 132 + cl]       = v0;
                    *(float2*)&smf[(r + 8) * 132 + cl] = v1;
                }
            }
        }
        __syncthreads();
        if (is_logits) {
            if (tid < 256) {
                int r = tid >> 1, hg = tid & 1;
                const float* row = smf + r * 132 + hg * 64;
                float v[64];
                float m = row[0];
                #pragma unroll
                for (int i = 0; i < 64; i++) { v[i] = row[i]; m = fmaxf(m, v[i]); }
                float ssum = 0.f;
                #pragma unroll
                for (int i = 0; i < 64; i++) { v[i] = expf(v[i] - m); ssum += v[i]; }
                float inv = 1.f / ssum;
                float* op = out + (size_t)(m0 + r) * NTOT + n0 + h * 128 + hg * 64;
                #pragma unroll
                for (int i = 0; i < 64; i += 4) {
                    float4 o = {v[i] * inv, v[i+1] * inv, v[i+2] * inv, v[i+3] * inv};
                    *(float4*)(op + i) = o;
                }
            }
        } else {
            for (int i = tid; i < 128 * 32; i += 512) {
                int r = i >> 5, c4 = (i & 31) * 4;
                float4 val = *(const float4*)&smf[r * 132 + c4];
                *(float4*)&out[(size_t)(m0 + r) * NTOT + n0 + h * 128 + c4] = val;
            }
        }
    }
}

// ---------------- 5. zero accumulators ----------------
__global__ void zero_kernel() {
    int i = blockIdx.x * blockDim.x + threadIdx.x;
    if (i < BATCH * DIM * HD) d_Num[i] = 0.f;
    if (i < BATCH * DIM)      d_C[i] = 0.f;
}

// ---------------- 6. Num = sum_s W*V, C = sum_s W ----------------
#define SCH 1024
__global__ __launch_bounds__(256) void accum_kernel() {
    int sc = blockIdx.x, h = blockIdx.y, b = blockIdx.z;
    __shared__ float Ws[32][64];
    __shared__ float Vs[32][64];
    int tid = threadIdx.x;
    int tk = (tid >> 4) * 4, td = (tid & 15) * 4;
    float acc[4][4] = {};
    float cs = 0.f;
    size_t base = ((size_t)b * SEQ + (size_t)sc * SCH) * NTOT + h * HD;
    for (int st = 0; st < SCH; st += 32) {
        #pragma unroll
        for (int l = 0; l < 2; l++) {
            int f = tid + l * 256;
            int r = f >> 4;
            int c = (f & 15) * 4;
            *(float4*)&Ws[r][c] = *(const float4*)&d_LV[base + (size_t)(st + r) * NTOT + c];
            *(float4*)&Vs[r][c] = *(const float4*)&d_LV[base + 512 + (size_t)(st + r) * NTOT + c];
        }
        __syncthreads();
        #pragma unroll 8
        for (int r = 0; r < 32; r++) {
            float wv[4], vv[4];
            *(float4*)&wv[0] = *(const float4*)&Ws[r][tk];
            *(float4*)&vv[0] = *(const float4*)&Vs[r][td];
            #pragma unroll
            for (int i = 0; i < 4; i++)
                #pragma unroll
                for (int j = 0; j < 4; j++)
                    acc[i][j] = fmaf(wv[i], vv[j], acc[i][j]);
        }
        if (tid < 64) {
            #pragma unroll
            for (int r = 0; r < 32; r++) cs += Ws[r][tid];
        }
        __syncthreads();
    }
    #pragma unroll
    for (int i = 0; i < 4; i++)
        #pragma unroll
        for (int j = 0; j < 4; j++)
            atomicAdd(&d_Num[((size_t)b * DIM + h * HD + tk + i) * HD + td + j], acc[i][j]);
    if (tid < 64) atomicAdd(&d_C[b * DIM + h * HD + tid], cs);
}

// ---------------- 7. divide, transpose, final LN ----------------
__global__ void final_kernel(const float* __restrict__ g,
                             const float* __restrict__ bb,
                             float* __restrict__ out) {
    __shared__ float sbuf[32];
    int blk = blockIdx.x;
    int b = blk >> 6, k = blk & 63;
    int tid = threadIdx.x;
    int h = tid >> 6, d = tid & 63;
    float c = d_C[b * DIM + h * HD + k];
    float v = d_Num[((size_t)b * DIM + h * HD + k) * HD + d] / (c + EPS_C);
    float mu = blockReduceSum(v, sbuf) * (1.f / DIM);
    float dv = v - mu;
    float var = blockReduceSum(dv * dv, sbuf) * (1.f / DIM);
    out[(size_t)blk * DIM + tid] = dv * rsqrtf(var + LN_EPS) * g[tid] + bb[tid];
}

// ---------------- launch ----------------
extern "C" void kernel_launch(void* const* d_in, const int* in_sizes, int n_in,
                              void* d_out, int out_size) {
    const float* X       = (const float*)d_in[0];
    const float* slots_w = (const float*)d_in[1];
    const float* g_slots = (const float*)d_in[2];
    const float* b_slots = (const float*)d_in[3];
    const float* Wk      = (const float*)d_in[4];
    const float* bk      = (const float*)d_in[5];
    const float* Wv      = (const float*)d_in[6];
    const float* bv      = (const float*)d_in[7];
    const float* g_after = (const float*)d_in[8];
    const float* b_after = (const float*)d_in[9];
    float* out = (float*)d_out;

    __half *pXh, *pWh;
    float *pbcat, *pLV;
    cudaGetSymbolAddress((void**)&pXh, d_Xh);
    cudaGetSymbolAddress((void**)&pWh, d_Wh);
    cudaGetSymbolAddress((void**)&pbcat, d_bcat);
    cudaGetSymbolAddress((void**)&pLV, d_LV);

    static bool attr_set = false;
    if (!attr_set) {
        cudaFuncSetAttribute(gemm_fp16, cudaFuncAttributeMaxDynamicSharedMemorySize, SMEM_BYTES);
        attr_set = true;
    }

    ln_slots_kernel<<<KSLOTS, DIM>>>(slots_w, g_slots, b_slots);
    fold_kernel<<<DIM, 256>>>(Wk, bk);
    convw_kernel<<<256, 256>>>(Wv, bv);
    convx_kernel<<<16384, 256>>>(X);

    dim3 ggrid(NTOT / NT, BT / MT);   // (4, 512)
    gemm_fp16<<<ggrid, 512, SMEM_BYTES>>>(pXh, pWh, pbcat, pLV);

    zero_kernel<<<(BATCH * DIM * HD + 255) / 256, 256>>>();
    accum_kernel<<<dim3(SEQ / SCH, HEADS, BATCH), 256>>>();
    final_kernel<<<BATCH * KSLOTS, DIM>>>(g_after, b_after, out);
}

// round 7
// speedup vs baseline: 3.8952x; 1.1189x over previous
#include <cuda_runtime.h>
#include <cuda_fp16.h>
#include <cstdint>

#define BATCH   8
#define SEQ     8192
#define BT      65536
#define DIM     512
#define HEADS   8
#define HD      64
#define KSLOTS  64
#define SCALE   0.125f
#define EPS_C   1e-20f
#define LN_EPS  1e-5f

#define NTOT    1024        // [logits(512) | V(512)]
#define MT      128
#define NT      256
#define KC      64          // k-chunk (halves)
#define NCHUNK  8           // 512/64

// ---------------- scratch ----------------
__device__ float d_S[KSLOTS * DIM];
__device__ float d_Weff[DIM * DIM];
__device__ float d_beff[DIM];
__device__ float d_bcat[NTOT];
__device__ __half d_Xh[(size_t)BT * DIM];
__device__ __half d_Wh[(size_t)NTOT * DIM];
__device__ __half d_LVh[(size_t)BT * NTOT];
__device__ float d_Num[BATCH * DIM * HD];
__device__ float d_C[BATCH * DIM];

// ---------------- helpers ----------------
__device__ __forceinline__ uint32_t s2u(const void* p) {
    uint32_t a;
    asm("{ .reg .u64 t; cvta.to.shared.u64 t, %1; cvt.u32.u64 %0, t; }" : "=r"(a) : "l"(p));
    return a;
}
// swizzled dword index within a [rows][32-dword] tile
#define SIDX(r, c) (((r) << 5) + ((c) ^ (((r) & 7) << 2)))

__device__ __forceinline__ uint4 pack8(float4 a, float4 b) {
    __half2 p0 = __floats2half2_rn(a.x, a.y);
    __half2 p1 = __floats2half2_rn(a.z, a.w);
    __half2 p2 = __floats2half2_rn(b.x, b.y);
    __half2 p3 = __floats2half2_rn(b.z, b.w);
    uint4 o;
    o.x = *(uint32_t*)&p0; o.y = *(uint32_t*)&p1;
    o.z = *(uint32_t*)&p2; o.w = *(uint32_t*)&p3;
    return o;
}

__device__ __forceinline__ void unpack8(uint4 u, float* o) {
    __half2* h = (__half2*)&u;
    float2 f0 = __half22float2(h[0]);
    float2 f1 = __half22float2(h[1]);
    float2 f2 = __half22float2(h[2]);
    float2 f3 = __half22float2(h[3]);
    o[0] = f0.x; o[1] = f0.y; o[2] = f1.x; o[3] = f1.y;
    o[4] = f2.x; o[5] = f2.y; o[6] = f3.x; o[7] = f3.y;
}

__device__ __forceinline__ float blockReduceSum(float v, float* sbuf) {
    #pragma unroll
    for (int o = 16; o > 0; o >>= 1) v += __shfl_down_sync(0xffffffffu, v, o);
    int lane = threadIdx.x & 31, w = threadIdx.x >> 5;
    if (lane == 0) sbuf[w] = v;
    __syncthreads();
    int nw = blockDim.x >> 5;
    v = (threadIdx.x < nw) ? sbuf[threadIdx.x] : 0.f;
    if (w == 0) {
        #pragma unroll
        for (int o = 16; o > 0; o >>= 1) v += __shfl_down_sync(0xffffffffu, v, o);
    }
    if (threadIdx.x == 0) sbuf[0] = v;
    __syncthreads();
    v = sbuf[0];
    __syncthreads();
    return v;
}

// ---------------- 1. layernorm slots ----------------
__global__ void ln_slots_kernel(const float* __restrict__ slots,
                                const float* __restrict__ g,
                                const float* __restrict__ b) {
    __shared__ float sbuf[32];
    int k = blockIdx.x, tid = threadIdx.x;
    float x = slots[k * DIM + tid];
    float mu = blockReduceSum(x, sbuf) * (1.f / DIM);
    float dv = x - mu;
    float var = blockReduceSum(dv * dv, sbuf) * (1.f / DIM);
    d_S[k * DIM + tid] = dv * rsqrtf(var + LN_EPS) * g[tid] + b[tid];
}

// ---------------- 2. fold Q into Wk ----------------
__global__ void fold_kernel(const float* __restrict__ Wk,
                            const float* __restrict__ bk) {
    int rk = blockIdx.x;
    int h = rk >> 6, k = rk & 63;
    __shared__ float sq[HD];
    int tid = threadIdx.x;
    if (tid < HD) sq[tid] = d_S[k * DIM + h * HD + tid];
    __syncthreads();
    for (int j = tid; j < DIM; j += blockDim.x) {
        float acc = 0.f;
        #pragma unroll
        for (int d = 0; d < HD; d++)
            acc = fmaf(sq[d], Wk[(size_t)(h * HD + d) * DIM + j], acc);
        d_Weff[(size_t)rk * DIM + j] = acc * SCALE;
    }
    if (tid == 0) {
        float acc = 0.f;
        #pragma unroll
        for (int d = 0; d < HD; d++) acc += sq[d] * bk[h * HD + d];
        d_beff[rk] = acc * SCALE;
    }
}

// ---------------- 3. merged fp32 -> fp16 conversion (X and [Weff;Wv]) ----------------
#define CONVX_BLKS 16384
__global__ void conv_all(const float* __restrict__ X,
                         const float* __restrict__ Wv,
                         const float* __restrict__ bv) {
    if (blockIdx.x < CONVX_BLKS) {
        size_t idx = (size_t)blockIdx.x * 256 + threadIdx.x;   // BT*DIM/8
        size_t base = idx * 8;
        float4 a = *(const float4*)&X[base];
        float4 b = *(const float4*)&X[base + 4];
        *(uint4*)&d_Xh[base] = pack8(a, b);
    } else {
        size_t idx = (size_t)(blockIdx.x - CONVX_BLKS) * 256 + threadIdx.x; // 65536
        int row = (int)(idx >> 6);
        int c8 = ((int)idx & 63) << 3;
        const float* src = (row < 512) ? &d_Weff[(size_t)row * DIM + c8]
                                       : &Wv[(size_t)(row - 512) * DIM + c8];
        float4 a = *(const float4*)src;
        float4 b = *(const float4*)(src + 4);
        *(uint4*)&d_Wh[(size_t)row * DIM + c8] = pack8(a, b);
        if (c8 == 0) d_bcat[row] = (row < 512) ? d_beff[row] : bv[row - 512];
    }
}

// ---------------- 4. fp16 mma.sync GEMM + fused softmax, fp16 output ----------------
#define SMD_A(s)     ((s) * 4096)
#define SMD_B(s)     (12288 + (s) * 8192)
#define SMD_BIAS     36864
#define SMEM_BYTES   ((36864 + 256) * 4)

__device__ __forceinline__ void load_chunk(uint32_t sb, const __half* __restrict__ Xh,
                                           const __half* __restrict__ Wh,
                                           int c, int s, int m0, int n0, int tid) {
    int kt = c * KC;
    uint32_t abase = sb + SMD_A(s) * 4;
    uint32_t bbase = sb + SMD_B(s) * 4;
    #pragma unroll
    for (int l = 0; l < 2; l++) {
        int t = tid + l * 512;
        int r = t >> 3, c8 = t & 7;
        uint32_t dst = abase + SIDX(r, c8 * 4) * 4;
        const __half* src = Xh + (size_t)(m0 + r) * DIM + kt + c8 * 8;
        asm volatile("cp.async.cg.shared.global [%0], [%1], 16;" :: "r"(dst), "l"(src));
    }
    #pragma unroll
    for (int l = 0; l < 4; l++) {
        int t = tid + l * 512;
        int r = t >> 3, c8 = t & 7;
        uint32_t dst = bbase + SIDX(r, c8 * 4) * 4;
        const __half* src = Wh + (size_t)(n0 + r) * DIM + kt + c8 * 8;
        asm volatile("cp.async.cg.shared.global [%0], [%1], 16;" :: "r"(dst), "l"(src));
    }
    asm volatile("cp.async.commit_group;" ::: "memory");
}

__global__ void __launch_bounds__(512) gemm_fp16(const __half* __restrict__ Xh,
                                                 const __half* __restrict__ Wh,
                                                 const float* __restrict__ bias,
                                                 __half* __restrict__ out) {
    extern __shared__ uint32_t sm32[];
    float* smf = (float*)sm32;
    uint32_t sb = s2u(sm32);
    const int tid = threadIdx.x;
    const int wid = tid >> 5, lane = tid & 31;
    const int g = lane >> 2, tg = lane & 3;
    const int wm = (wid & 3) * 32;
    const int wn = (wid >> 2) * 64;
    const int m0 = blockIdx.y * MT;
    const int n0 = blockIdx.x * NT;

    if (tid < NT) smf[SMD_BIAS + tid] = bias[n0 + tid];

    float d[2][8][4];
    #pragma unroll
    for (int mt = 0; mt < 2; mt++)
        #pragma unroll
        for (int nt = 0; nt < 8; nt++)
            #pragma unroll
            for (int i = 0; i < 4; i++) d[mt][nt][i] = 0.f;

    load_chunk(sb, Xh, Wh, 0, 0, m0, n0, tid);
    load_chunk(sb, Xh, Wh, 1, 1, m0, n0, tid);

    for (int c = 0; c < NCHUNK; c++) {
        int s = c % 3;
        if (c + 2 < NCHUNK) load_chunk(sb, Xh, Wh, c + 2, (c + 2) % 3, m0, n0, tid);
        if (c <= NCHUNK - 3)      asm volatile("cp.async.wait_group 2;" ::: "memory");
        else if (c == NCHUNK - 2) asm volatile("cp.async.wait_group 1;" ::: "memory");
        else                      asm volatile("cp.async.wait_group 0;" ::: "memory");
        __syncthreads();

        const uint32_t* As = sm32 + SMD_A(s);
        const uint32_t* Bs = sm32 + SMD_B(s);
        #pragma unroll
        for (int ks = 0; ks < 4; ks++) {
            int kd = ks * 8;
            uint32_t a[2][4], b[8][2];
            #pragma unroll
            for (int mt = 0; mt < 2; mt++) {
                int r = wm + mt * 16 + g;
                a[mt][0] = As[SIDX(r,     kd + tg)];
                a[mt][1] = As[SIDX(r + 8, kd + tg)];
                a[mt][2] = As[SIDX(r,     kd + tg + 4)];
                a[mt][3] = As[SIDX(r + 8, kd + tg + 4)];
            }
            #pragma unroll
            for (int nt = 0; nt < 8; nt++) {
                int n = wn + nt * 8 + g;
                b[nt][0] = Bs[SIDX(n, kd + tg)];
                b[nt][1] = Bs[SIDX(n, kd + tg + 4)];
            }
            #pragma unroll
            for (int mt = 0; mt < 2; mt++)
                #pragma unroll
                for (int nt = 0; nt < 8; nt++)
                    asm volatile(
                        "mma.sync.aligned.m16n8k16.row.col.f32.f16.f16.f32 "
                        "{%0,%1,%2,%3}, {%4,%5,%6,%7}, {%8,%9}, {%0,%1,%2,%3};"
                        : "+f"(d[mt][nt][0]), "+f"(d[mt][nt][1]),
                          "+f"(d[mt][nt][2]), "+f"(d[mt][nt][3])
                        : "r"(a[mt][0]), "r"(a[mt][1]), "r"(a[mt][2]), "r"(a[mt][3]),
                          "r"(b[nt][0]), "r"(b[nt][1]));
        }
        __syncthreads();
    }

    // ---------------- epilogue: bias + (softmax for logits), fp16 store
    const bool is_logits = (blockIdx.x < 2);
    const int wn_local = ((wid >> 2) & 1) * 64;
    #pragma unroll 1
    for (int h = 0; h < 2; h++) {
        __syncthreads();
        if ((wid >> 3) == h) {
            #pragma unroll
            for (int mt = 0; mt < 2; mt++) {
                int r = wm + mt * 16 + g;
                #pragma unroll
                for (int nt = 0; nt < 8; nt++) {
                    int cl = wn_local + nt * 8 + tg * 2;
                    float b0 = smf[SMD_BIAS + h * 128 + cl];
                    float b1 = smf[SMD_BIAS + h * 128 + cl + 1];
                    float2 v0 = {d[mt][nt][0] + b0, d[mt][nt][1] + b1};
                    float2 v1 = {d[mt][nt][2] + b0, d[mt][nt][3] + b1};
                    *(float2*)&smf[r * 132 + cl]       = v0;
                    *(float2*)&smf[(r + 8) * 132 + cl] = v1;
                }
            }
        }
        __syncthreads();
        if (is_logits) {
            if (tid < 256) {
                int r = tid >> 1, hg = tid & 1;
                const float* row = smf + r * 132 + hg * 64;
                float v[64];
                float m = row[0];
                #pragma unroll
                for (int i = 0; i < 64; i++) { v[i] = row[i]; m = fmaxf(m, v[i]); }
                float ssum = 0.f;
                #pragma unroll
                for (int i = 0; i < 64; i++) { v[i] = expf(v[i] - m); ssum += v[i]; }
                float inv = 1.f / ssum;
                __half* op = out + (size_t)(m0 + r) * NTOT + n0 + h * 128 + hg * 64;
                #pragma unroll
                for (int i = 0; i < 64; i += 8) {
                    float4 a = {v[i] * inv, v[i+1] * inv, v[i+2] * inv, v[i+3] * inv};
                    float4 b = {v[i+4] * inv, v[i+5] * inv, v[i+6] * inv, v[i+7] * inv};
                    *(uint4*)(op + i) = pack8(a, b);
                }
            }
        } else {
            for (int i = tid; i < 128 * 16; i += 512) {
                int r = i >> 4, c8 = (i & 15) * 8;
                float4 a = *(const float4*)&smf[r * 132 + c8];
                float4 b = *(const float4*)&smf[r * 132 + c8 + 4];
                *(uint4*)&out[(size_t)(m0 + r) * NTOT + n0 + h * 128 + c8] = pack8(a, b);
            }
        }
    }
}

// ---------------- 5. zero accumulators ----------------
__global__ void zero_kernel() {
    int i = blockIdx.x * blockDim.x + threadIdx.x;
    if (i < BATCH * DIM * HD) d_Num[i] = 0.f;
    if (i < BATCH * DIM)      d_C[i] = 0.f;
}

// ---------------- 6. Num = sum_s W*V, C = sum_s W (fp16 in, fp32 math) ----------------
#define SCH 1024
__global__ __launch_bounds__(256) void accum_kernel() {
    int sc = blockIdx.x, h = blockIdx.y, b = blockIdx.z;
    __shared__ float Ws[32][64];
    __shared__ float Vs[32][64];
    int tid = threadIdx.x;
    int tk = (tid >> 4) * 4, td = (tid & 15) * 4;
    float acc[4][4] = {};
    float cs = 0.f;
    size_t base = ((size_t)b * SEQ + (size_t)sc * SCH) * NTOT + h * HD;
    for (int st = 0; st < SCH; st += 32) {
        {
            int r = tid >> 3, c = (tid & 7) * 8;
            uint4 w = *(const uint4*)&d_LVh[base + (size_t)(st + r) * NTOT + c];
            uint4 v = *(const uint4*)&d_LVh[base + 512 + (size_t)(st + r) * NTOT + c];
            float tmp[8];
            unpack8(w, tmp);
            *(float4*)&Ws[r][c] = *(float4*)&tmp[0];
            *(float4*)&Ws[r][c + 4] = *(float4*)&tmp[4];
            unpack8(v, tmp);
            *(float4*)&Vs[r][c] = *(float4*)&tmp[0];
            *(float4*)&Vs[r][c + 4] = *(float4*)&tmp[4];
        }
        __syncthreads();
        #pragma unroll 8
        for (int r = 0; r < 32; r++) {
            float wv[4], vv[4];
            *(float4*)&wv[0] = *(const float4*)&Ws[r][tk];
            *(float4*)&vv[0] = *(const float4*)&Vs[r][td];
            #pragma unroll
            for (int i = 0; i < 4; i++)
                #pragma unroll
                for (int j = 0; j < 4; j++)
                    acc[i][j] = fmaf(wv[i], vv[j], acc[i][j]);
        }
        if (tid < 64) {
            #pragma unroll
            for (int r = 0; r < 32; r++) cs += Ws[r][tid];
        }
        __syncthreads();
    }
    #pragma unroll
    for (int i = 0; i < 4; i++)
        #pragma unroll
        for (int j = 0; j < 4; j++)
            atomicAdd(&d_Num[((size_t)b * DIM + h * HD + tk + i) * HD + td + j], acc[i][j]);
    if (tid < 64) atomicAdd(&d_C[b * DIM + h * HD + tid], cs);
}

// ---------------- 7. divide, transpose, final LN ----------------
__global__ void final_kernel(const float* __restrict__ g,
                             const float* __restrict__ bb,
                             float* __restrict__ out) {
    __shared__ float sbuf[32];
    int blk = blockIdx.x;
    int b = blk >> 6, k = blk & 63;
    int tid = threadIdx.x;
    int h = tid >> 6, d = tid & 63;
    float c = d_C[b * DIM + h * HD + k];
    float v = d_Num[((size_t)b * DIM + h * HD + k) * HD + d] / (c + EPS_C);
    float mu = blockReduceSum(v, sbuf) * (1.f / DIM);
    float dv = v - mu;
    float var = blockReduceSum(dv * dv, sbuf) * (1.f / DIM);
    out[(size_t)blk * DIM + tid] = dv * rsqrtf(var + LN_EPS) * g[tid] + bb[tid];
}

// ---------------- launch ----------------
extern "C" void kernel_launch(void* const* d_in, const int* in_sizes, int n_in,
                              void* d_out, int out_size) {
    const float* X       = (const float*)d_in[0];
    const float* slots_w = (const float*)d_in[1];
    const float* g_slots = (const float*)d_in[2];
    const float* b_slots = (const float*)d_in[3];
    const float* Wk      = (const float*)d_in[4];
    const float* bk      = (const float*)d_in[5];
    const float* Wv      = (const float*)d_in[6];
    const float* bv      = (const float*)d_in[7];
    const float* g_after = (const float*)d_in[8];
    const float* b_after = (const float*)d_in[9];
    float* out = (float*)d_out;

    __half *pXh, *pWh, *pLVh;
    float *pbcat;
    cudaGetSymbolAddress((void**)&pXh, d_Xh);
    cudaGetSymbolAddress((void**)&pWh, d_Wh);
    cudaGetSymbolAddress((void**)&pbcat, d_bcat);
    cudaGetSymbolAddress((void**)&pLVh, d_LVh);

    static bool attr_set = false;
    if (!attr_set) {
        cudaFuncSetAttribute(gemm_fp16, cudaFuncAttributeMaxDynamicSharedMemorySize, SMEM_BYTES);
        attr_set = true;
    }

    ln_slots_kernel<<<KSLOTS, DIM>>>(slots_w, g_slots, b_slots);
    fold_kernel<<<DIM, 256>>>(Wk, bk);
    conv_all<<<CONVX_BLKS + 256, 256>>>(X, Wv, bv);

    dim3 ggrid(NTOT / NT, BT / MT);   // (4, 512)
    gemm_fp16<<<ggrid, 512, SMEM_BYTES>>>(pXh, pWh, pbcat, pLVh);

    zero_kernel<<<(BATCH * DIM * HD + 255) / 256, 256>>>();
    accum_kernel<<<dim3(SEQ / SCH, HEADS, BATCH), 256>>>();
    final_kernel<<<BATCH * KSLOTS, DIM>>>(g_after, b_after, out);
}

// round 9
// speedup vs baseline: 5.0218x; 1.2892x over previous
#include <cuda_runtime.h>
#include <cuda_fp16.h>
#include <cstdint>

#define BATCH   8
#define SEQ     8192
#define BT      65536
#define DIM     512
#define HEADS   8
#define HD      64
#define KSLOTS  64
#define SCALE   0.125f
#define EPS_C   1e-20f
#define LN_EPS  1e-5f

#define NTOT    1024        // [logits(512) | V(512)]
#define MT      128
#define NT      256
#define KC      64          // k-chunk (halves)
#define NCHUNK  8           // 512/64

// ---------------- scratch ----------------
__device__ float d_S[KSLOTS * DIM];
__device__ float d_Weff[DIM * DIM];
__device__ float d_beff[DIM];
__device__ float d_bcat[NTOT];
__device__ __half d_Xh[(size_t)BT * DIM];
__device__ __half d_Wh[(size_t)NTOT * DIM];
__device__ __half d_LVh[(size_t)BT * NTOT];
__device__ float d_Num[BATCH * DIM * HD];
__device__ float d_C[BATCH * DIM];

// ---------------- helpers ----------------
__device__ __forceinline__ uint32_t s2u(const void* p) {
    uint32_t a;
    asm("{ .reg .u64 t; cvta.to.shared.u64 t, %1; cvt.u32.u64 %0, t; }" : "=r"(a) : "l"(p));
    return a;
}
// swizzled dword index within a [rows][32-dword] tile
#define SIDX(r, c) (((r) << 5) + ((c) ^ (((r) & 7) << 2)))

#define LDSM4(r0, r1, r2, r3, addr) \
    asm volatile("ldmatrix.sync.aligned.m8n8.x4.shared.b16 {%0,%1,%2,%3}, [%4];" \
        : "=r"(r0), "=r"(r1), "=r"(r2), "=r"(r3) : "r"(addr))

#define LDSM4T(r0, r1, r2, r3, addr) \
    asm volatile("ldmatrix.sync.aligned.m8n8.x4.trans.shared.b16 {%0,%1,%2,%3}, [%4];" \
        : "=r"(r0), "=r"(r1), "=r"(r2), "=r"(r3) : "r"(addr))

#define MMA16816(d, a, b0, b1) \
    asm volatile( \
        "mma.sync.aligned.m16n8k16.row.col.f32.f16.f16.f32 " \
        "{%0,%1,%2,%3}, {%4,%5,%6,%7}, {%8,%9}, {%0,%1,%2,%3};" \
        : "+f"((d)[0]), "+f"((d)[1]), "+f"((d)[2]), "+f"((d)[3]) \
        : "r"((a)[0]), "r"((a)[1]), "r"((a)[2]), "r"((a)[3]), "r"(b0), "r"(b1))

__device__ __forceinline__ uint4 pack8(float4 a, float4 b) {
    __half2 p0 = __floats2half2_rn(a.x, a.y);
    __half2 p1 = __floats2half2_rn(a.z, a.w);
    __half2 p2 = __floats2half2_rn(b.x, b.y);
    __half2 p3 = __floats2half2_rn(b.z, b.w);
    uint4 o;
    o.x = *(uint32_t*)&p0; o.y = *(uint32_t*)&p1;
    o.z = *(uint32_t*)&p2; o.w = *(uint32_t*)&p3;
    return o;
}

__device__ __forceinline__ float blockReduceSum(float v, float* sbuf) {
    #pragma unroll
    for (int o = 16; o > 0; o >>= 1) v += __shfl_down_sync(0xffffffffu, v, o);
    int lane = threadIdx.x & 31, w = threadIdx.x >> 5;
    if (lane == 0) sbuf[w] = v;
    __syncthreads();
    int nw = blockDim.x >> 5;
    v = (threadIdx.x < nw) ? sbuf[threadIdx.x] : 0.f;
    if (w == 0) {
        #pragma unroll
        for (int o = 16; o > 0; o >>= 1) v += __shfl_down_sync(0xffffffffu, v, o);
    }
    if (threadIdx.x == 0) sbuf[0] = v;
    __syncthreads();
    v = sbuf[0];
    __syncthreads();
    return v;
}

// ---------------- 1. layernorm slots ----------------
__global__ void ln_slots_kernel(const float* __restrict__ slots,
                                const float* __restrict__ g,
                                const float* __restrict__ b) {
    __shared__ float sbuf[32];
    int k = blockIdx.x, tid = threadIdx.x;
    float x = slots[k * DIM + tid];
    float mu = blockReduceSum(x, sbuf) * (1.f / DIM);
    float dv = x - mu;
    float var = blockReduceSum(dv * dv, sbuf) * (1.f / DIM);
    d_S[k * DIM + tid] = dv * rsqrtf(var + LN_EPS) * g[tid] + b[tid];
}

// ---------------- 2. fold Q into Wk ----------------
__global__ void fold_kernel(const float* __restrict__ Wk,
                            const float* __restrict__ bk) {
    int rk = blockIdx.x;
    int h = rk >> 6, k = rk & 63;
    __shared__ float sq[HD];
    int tid = threadIdx.x;
    if (tid < HD) sq[tid] = d_S[k * DIM + h * HD + tid];
    __syncthreads();
    for (int j = tid; j < DIM; j += blockDim.x) {
        float acc = 0.f;
        #pragma unroll
        for (int d = 0; d < HD; d++)
            acc = fmaf(sq[d], Wk[(size_t)(h * HD + d) * DIM + j], acc);
        d_Weff[(size_t)rk * DIM + j] = acc * SCALE;
    }
    if (tid == 0) {
        float acc = 0.f;
        #pragma unroll
        for (int d = 0; d < HD; d++) acc += sq[d] * bk[h * HD + d];
        d_beff[rk] = acc * SCALE;
    }
}

// ---------------- 3. merged fp32 -> fp16 conversion ----------------
#define CONVX_BLKS 16384
__global__ void conv_all(const float* __restrict__ X,
                         const float* __restrict__ Wv,
                         const float* __restrict__ bv) {
    if (blockIdx.x < CONVX_BLKS) {
        size_t idx = (size_t)blockIdx.x * 256 + threadIdx.x;
        size_t base = idx * 8;
        float4 a = *(const float4*)&X[base];
        float4 b = *(const float4*)&X[base + 4];
        *(uint4*)&d_Xh[base] = pack8(a, b);
    } else {
        size_t idx = (size_t)(blockIdx.x - CONVX_BLKS) * 256 + threadIdx.x;
        int row = (int)(idx >> 6);
        int c8 = ((int)idx & 63) << 3;
        const float* src = (row < 512) ? &d_Weff[(size_t)row * DIM + c8]
                                       : &Wv[(size_t)(row - 512) * DIM + c8];
        float4 a = *(const float4*)src;
        float4 b = *(const float4*)(src + 4);
        *(uint4*)&d_Wh[(size_t)row * DIM + c8] = pack8(a, b);
        if (c8 == 0) d_bcat[row] = (row < 512) ? d_beff[row] : bv[row - 512];
    }
}

// ---------------- 4. fp16 mma GEMM (ldmatrix) + fused softmax ----------------
#define SMD_A(s)     ((s) * 4096)
#define SMD_B(s)     (12288 + (s) * 8192)
#define SMD_BIAS     36864
#define SMEM_BYTES   ((36864 + 256) * 4)

__device__ __forceinline__ void load_chunk(uint32_t sb, const __half* __restrict__ Xh,
                                           const __half* __restrict__ Wh,
                                           int c, int s, int m0, int n0, int tid) {
    int kt = c * KC;
    uint32_t abase = sb + SMD_A(s) * 4;
    uint32_t bbase = sb + SMD_B(s) * 4;
    #pragma unroll
    for (int l = 0; l < 2; l++) {
        int t = tid + l * 512;
        int r = t >> 3, c8 = t & 7;
        uint32_t dst = abase + SIDX(r, c8 * 4) * 4;
        const __half* src = Xh + (size_t)(m0 + r) * DIM + kt + c8 * 8;
        asm volatile("cp.async.cg.shared.global [%0], [%1], 16;" :: "r"(dst), "l"(src));
    }
    #pragma unroll
    for (int l = 0; l < 4; l++) {
        int t = tid + l * 512;
        int r = t >> 3, c8 = t & 7;
        uint32_t dst = bbase + SIDX(r, c8 * 4) * 4;
        const __half* src = Wh + (size_t)(n0 + r) * DIM + kt + c8 * 8;
        asm volatile("cp.async.cg.shared.global [%0], [%1], 16;" :: "r"(dst), "l"(src));
    }
    asm volatile("cp.async.commit_group;" ::: "memory");
}

__global__ void __launch_bounds__(512) gemm_fp16(const __half* __restrict__ Xh,
                                                 const __half* __restrict__ Wh,
                                                 const float* __restrict__ bias,
                                                 __half* __restrict__ out) {
    extern __shared__ uint32_t sm32[];
    float* smf = (float*)sm32;
    uint32_t sb = s2u(sm32);
    const int tid = threadIdx.x;
    const int wid = tid >> 5, lane = tid & 31;
    const int g = lane >> 2, tg = lane & 3;
    const int q1 = (lane >> 3) & 1;     // +8-row select
    const int q2 = lane >> 4;           // k-chunk select
    const int wm = (wid & 3) * 32;
    const int wn = (wid >> 2) * 64;
    const int m0 = blockIdx.y * MT;
    const int n0 = blockIdx.x * NT;

    if (tid < NT) smf[SMD_BIAS + tid] = bias[n0 + tid];

    float d[2][8][4];
    #pragma unroll
    for (int mt = 0; mt < 2; mt++)
        #pragma unroll
        for (int nt = 0; nt < 8; nt++)
            #pragma unroll
            for (int i = 0; i < 4; i++) d[mt][nt][i] = 0.f;

    load_chunk(sb, Xh, Wh, 0, 0, m0, n0, tid);
    load_chunk(sb, Xh, Wh, 1, 1, m0, n0, tid);

    for (int c = 0; c < NCHUNK; c++) {
        int s = c % 3;
        if (c + 2 < NCHUNK) load_chunk(sb, Xh, Wh, c + 2, (c + 2) % 3, m0, n0, tid);
        if (c <= NCHUNK - 3)      asm volatile("cp.async.wait_group 2;" ::: "memory");
        else if (c == NCHUNK - 2) asm volatile("cp.async.wait_group 1;" ::: "memory");
        else                      asm volatile("cp.async.wait_group 0;" ::: "memory");
        __syncthreads();

        #pragma unroll
        for (int ks = 0; ks < 4; ks++) {
            int kd = ks * 8;
            int dcol = kd + q2 * 4;
            uint32_t a[2][4], bfr[8][2];
            #pragma unroll
            for (int mt = 0; mt < 2; mt++) {
                int row = wm + mt * 16 + q1 * 8 + (lane & 7);
                uint32_t ad = sb + (SMD_A(s) + SIDX(row, dcol)) * 4;
                LDSM4(a[mt][0], a[mt][1], a[mt][2], a[mt][3], ad);
            }
            #pragma unroll
            for (int p = 0; p < 4; p++) {
                int row = wn + p * 16 + q1 * 8 + (lane & 7);
                uint32_t bd = sb + (SMD_B(s) + SIDX(row, dcol)) * 4;
                LDSM4(bfr[2*p][0], bfr[2*p+1][0], bfr[2*p][1], bfr[2*p+1][1], bd);
            }
            #pragma unroll
            for (int mt = 0; mt < 2; mt++)
                #pragma unroll
                for (int nt = 0; nt < 8; nt++)
                    MMA16816(d[mt][nt], a[mt], bfr[nt][0], bfr[nt][1]);
        }
        __syncthreads();
    }

    // ---------------- epilogue: bias + (softmax for logits), fp16 store
    const bool is_logits = (blockIdx.x < 2);
    const int wn_local = ((wid >> 2) & 1) * 64;
    #pragma unroll 1
    for (int h = 0; h < 2; h++) {
        __syncthreads();
        if ((wid >> 3) == h) {
            #pragma unroll
            for (int mt = 0; mt < 2; mt++) {
                int r = wm + mt * 16 + g;
                #pragma unroll
                for (int nt = 0; nt < 8; nt++) {
                    int cl = wn_local + nt * 8 + tg * 2;
                    float b0 = smf[SMD_BIAS + h * 128 + cl];
                    float b1 = smf[SMD_BIAS + h * 128 + cl + 1];
                    float2 v0 = {d[mt][nt][0] + b0, d[mt][nt][1] + b1};
                    float2 v1 = {d[mt][nt][2] + b0, d[mt][nt][3] + b1};
                    *(float2*)&smf[r * 132 + cl]       = v0;
                    *(float2*)&smf[(r + 8) * 132 + cl] = v1;
                }
            }
        }
        __syncthreads();
        if (is_logits) {
            if (tid < 256) {
                int r = tid >> 1, hg = tid & 1;
                const float* row = smf + r * 132 + hg * 64;
                float v[64];
                float m = row[0];
                #pragma unroll
                for (int i = 0; i < 64; i++) { v[i] = row[i]; m = fmaxf(m, v[i]); }
                float ssum = 0.f;
                #pragma unroll
                for (int i = 0; i < 64; i++) { v[i] = expf(v[i] - m); ssum += v[i]; }
                float inv = 1.f / ssum;
                __half* op = out + (size_t)(m0 + r) * NTOT + n0 + h * 128 + hg * 64;
                #pragma unroll
                for (int i = 0; i < 64; i += 8) {
                    float4 a = {v[i] * inv, v[i+1] * inv, v[i+2] * inv, v[i+3] * inv};
                    float4 b = {v[i+4] * inv, v[i+5] * inv, v[i+6] * inv, v[i+7] * inv};
                    *(uint4*)(op + i) = pack8(a, b);
                }
            }
        } else {
            for (int i = tid; i < 128 * 16; i += 512) {
                int r = i >> 4, c8 = (i & 15) * 8;
                float4 a = *(const float4*)&smf[r * 132 + c8];
                float4 b = *(const float4*)&smf[r * 132 + c8 + 4];
                *(uint4*)&out[(size_t)(m0 + r) * NTOT + n0 + h * 128 + c8] = pack8(a, b);
            }
        }
    }
}

// ---------------- 5. zero accumulators ----------------
__global__ void zero_kernel() {
    int i = blockIdx.x * blockDim.x + threadIdx.x;
    if (i < BATCH * DIM * HD) d_Num[i] = 0.f;
    if (i < BATCH * DIM)      d_C[i] = 0.f;
}

// ---------------- 6. tensor-core accum: Num = W^T V, C = colsum(W) ----------------
__device__ __forceinline__ void acc_load(uint32_t wbase, uint32_t vbase,
                                         size_t grow0, int h, int ch, int buf, int tid) {
    #pragma unroll
    for (int l = 0; l < 4; l++) {
        int t = tid + l * 128;
        int r = t >> 3, cc = t & 7;
        size_t ga = (grow0 + (size_t)ch * 64 + r) * NTOT + h * HD + cc * 8;
        uint32_t off = ((uint32_t)buf * 4096 + r * 64 + ((cc ^ (r & 7)) * 8)) * 2;
        asm volatile("cp.async.cg.shared.global [%0], [%1], 16;"
                     :: "r"(wbase + off), "l"(d_LVh + ga));
        asm volatile("cp.async.cg.shared.global [%0], [%1], 16;"
                     :: "r"(vbase + off), "l"(d_LVh + ga + 512));
    }
    asm volatile("cp.async.commit_group;" ::: "memory");
}

// grid (8 sc, 8 h, 8 b), 128 threads. Tiles of 64 s staged in smem, ldmatrix.trans.
__global__ __launch_bounds__(128) void accum_mma() {
    __shared__ __half Wst[2][64 * 64];
    __shared__ __half Vst[2][64 * 64];
    int sc = blockIdx.x, h = blockIdx.y, b = blockIdx.z;
    int tid = threadIdx.x, warp = tid >> 5, lane = tid & 31;
    int q1 = (lane >> 3) & 1, q2 = lane >> 4;
    uint32_t wbase = s2u(Wst), vbase = s2u(Vst);
    size_t grow0 = (size_t)b * SEQ + sc * 1024;

    float acc[8][4];
    #pragma unroll
    for (int nt = 0; nt < 8; nt++)
        #pragma unroll
        for (int i = 0; i < 4; i++) acc[nt][i] = 0.f;
    float cacc0 = 0.f, cacc1 = 0.f;

    acc_load(wbase, vbase, grow0, h, 0, 0, tid);
    for (int ch = 0; ch < 16; ch++) {
        int buf = ch & 1;
        if (ch + 1 < 16) {
            acc_load(wbase, vbase, grow0, h, ch + 1, buf ^ 1, tid);
            asm volatile("cp.async.wait_group 1;" ::: "memory");
        } else {
            asm volatile("cp.async.wait_group 0;" ::: "memory");
        }
        __syncthreads();
        #pragma unroll
        for (int ks = 0; ks < 4; ks++) {
            int s_loc = ks * 16 + q2 * 8 + (lane & 7);
            uint32_t a[4];
            {
                int cc = warp * 2 + q1;
                uint32_t ad = wbase + ((uint32_t)buf * 4096 + s_loc * 64 + ((cc ^ (s_loc & 7)) * 8)) * 2;
                LDSM4T(a[0], a[1], a[2], a[3], ad);
            }
            {   // slot-sum of W from A fragments
                float2 f;
                f = __half22float2(*(__half2*)&a[0]); cacc0 += f.x + f.y;
                f = __half22float2(*(__half2*)&a[2]); cacc0 += f.x + f.y;
                f = __half22float2(*(__half2*)&a[1]); cacc1 += f.x + f.y;
                f = __half22float2(*(__half2*)&a[3]); cacc1 += f.x + f.y;
            }
            #pragma unroll
            for (int p = 0; p < 4; p++) {
                uint32_t r0, r1, r2, r3;
                int cc = p * 2 + q1;
                uint32_t vd = vbase + ((uint32_t)buf * 4096 + s_loc * 64 + ((cc ^ (s_loc & 7)) * 8)) * 2;
                LDSM4T(r0, r1, r2, r3, vd);
                MMA16816(acc[2*p],     a, r0, r2);
                MMA16816(acc[2*p + 1], a, r1, r3);
            }
        }
        __syncthreads();
    }

    // reduce C across the 4 s-column lanes
    cacc0 += __shfl_xor_sync(0xffffffffu, cacc0, 1);
    cacc0 += __shfl_xor_sync(0xffffffffu, cacc0, 2);
    cacc1 += __shfl_xor_sync(0xffffffffu, cacc1, 1);
    cacc1 += __shfl_xor_sync(0xffffffffu, cacc1, 2);
    int slot0 = warp * 16 + (lane >> 2);
    if ((lane & 3) == 0) {
        atomicAdd(&d_C[b * DIM + h * HD + slot0],     cacc0);
        atomicAdd(&d_C[b * DIM + h * HD + slot0 + 8], cacc1);
    }
    #pragma unroll
    for (int nt = 0; nt < 8; nt++) {
        int dc = nt * 8 + (lane & 3) * 2;
        float* p0 = &d_Num[((size_t)b * DIM + h * HD + slot0) * HD + dc];
        float* p1 = &d_Num[((size_t)b * DIM + h * HD + slot0 + 8) * HD + dc];
        atomicAdd(p0,     acc[nt][0]);
        atomicAdd(p0 + 1, acc[nt][1]);
        atomicAdd(p1,     acc[nt][2]);
        atomicAdd(p1 + 1, acc[nt][3]);
    }
}

// ---------------- 7. divide, transpose, final LN ----------------
__global__ void final_kernel(const float* __restrict__ g,
                             const float* __restrict__ bb,
                             float* __restrict__ out) {
    __shared__ float sbuf[32];
    int blk = blockIdx.x;
    int b = blk >> 6, k = blk & 63;
    int tid = threadIdx.x;
    int h = tid >> 6, d = tid & 63;
    float c = d_C[b * DIM + h * HD + k];
    float v = d_Num[((size_t)b * DIM + h * HD + k) * HD + d] / (c + EPS_C);
    float mu = blockReduceSum(v, sbuf) * (1.f / DIM);
    float dv = v - mu;
    float var = blockReduceSum(dv * dv, sbuf) * (1.f / DIM);
    out[(size_t)blk * DIM + tid] = dv * rsqrtf(var + LN_EPS) * g[tid] + bb[tid];
}

// ---------------- launch ----------------
extern "C" void kernel_launch(void* const* d_in, const int* in_sizes, int n_in,
                              void* d_out, int out_size) {
    const float* X       = (const float*)d_in[0];
    const float* slots_w = (const float*)d_in[1];
    const float* g_slots = (const float*)d_in[2];
    const float* b_slots = (const float*)d_in[3];
    const float* Wk      = (const float*)d_in[4];
    const float* bk      = (const float*)d_in[5];
    const float* Wv      = (const float*)d_in[6];
    const float* bv      = (const float*)d_in[7];
    const float* g_after = (const float*)d_in[8];
    const float* b_after = (const float*)d_in[9];
    float* out = (float*)d_out;

    __half *pXh, *pWh, *pLVh;
    float *pbcat;
    cudaGetSymbolAddress((void**)&pXh, d_Xh);
    cudaGetSymbolAddress((void**)&pWh, d_Wh);
    cudaGetSymbolAddress((void**)&pbcat, d_bcat);
    cudaGetSymbolAddress((void**)&pLVh, d_LVh);

    static bool attr_set = false;
    if (!attr_set) {
        cudaFuncSetAttribute(gemm_fp16, cudaFuncAttributeMaxDynamicSharedMemorySize, SMEM_BYTES);
        attr_set = true;
    }

    ln_slots_kernel<<<KSLOTS, DIM>>>(slots_w, g_slots, b_slots);
    fold_kernel<<<DIM, 256>>>(Wk, bk);
    conv_all<<<CONVX_BLKS + 256, 256>>>(X, Wv, bv);

    dim3 ggrid(NTOT / NT, BT / MT);   // (4, 512)
    gemm_fp16<<<ggrid, 512, SMEM_BYTES>>>(pXh, pWh, pbcat, pLVh);

    zero_kernel<<<(BATCH * DIM * HD + 255) / 256, 256>>>();
    accum_mma<<<dim3(8, HEADS, BATCH), 128>>>();
    final_kernel<<<BATCH * KSLOTS, DIM>>>(g_after, b_after, out);
}

// round 11
// speedup vs baseline: 5.9544x; 1.1857x over previous
#include <cuda_runtime.h>
#include <cuda_fp16.h>
#include <cstdint>

#define BATCH   8
#define SEQ     8192
#define BT      65536
#define DIM     512
#define HEADS   8
#define HD      64
#define KSLOTS  64
#define SCALE   0.125f
#define EPS_C   1e-20f
#define LN_EPS  1e-5f

#define NTOT    1024        // [logits(512) | V(512)]
#define MT      128
#define NT      128
#define KC      64          // k-chunk (halves)
#define NCHUNK  8           // 512/64

// ---------------- scratch ----------------
__device__ float d_S[KSLOTS * DIM];
__device__ float d_Weff[DIM * DIM];
__device__ float d_beff[DIM];
__device__ float d_bcat[NTOT];
__device__ __half d_Xh[(size_t)BT * DIM];
__device__ __half d_Wh[(size_t)NTOT * DIM];
__device__ __half d_LVh[(size_t)BT * NTOT];
__device__ float d_Num[BATCH * DIM * HD];
__device__ float d_C[BATCH * DIM];

// ---------------- helpers ----------------
__device__ __forceinline__ uint32_t s2u(const void* p) {
    uint32_t a;
    asm("{ .reg .u64 t; cvta.to.shared.u64 t, %1; cvt.u32.u64 %0, t; }" : "=r"(a) : "l"(p));
    return a;
}
// swizzled dword index within a [rows][32-dword] tile
#define SIDX(r, c) (((r) << 5) + ((c) ^ (((r) & 7) << 2)))

#define LDSM4(r0, r1, r2, r3, addr) \
    asm volatile("ldmatrix.sync.aligned.m8n8.x4.shared.b16 {%0,%1,%2,%3}, [%4];" \
        : "=r"(r0), "=r"(r1), "=r"(r2), "=r"(r3) : "r"(addr))

#define LDSM4T(r0, r1, r2, r3, addr) \
    asm volatile("ldmatrix.sync.aligned.m8n8.x4.trans.shared.b16 {%0,%1,%2,%3}, [%4];" \
        : "=r"(r0), "=r"(r1), "=r"(r2), "=r"(r3) : "r"(addr))

#define MMA16816(d, a, b0, b1) \
    asm volatile( \
        "mma.sync.aligned.m16n8k16.row.col.f32.f16.f16.f32 " \
        "{%0,%1,%2,%3}, {%4,%5,%6,%7}, {%8,%9}, {%0,%1,%2,%3};" \
        : "+f"((d)[0]), "+f"((d)[1]), "+f"((d)[2]), "+f"((d)[3]) \
        : "r"((a)[0]), "r"((a)[1]), "r"((a)[2]), "r"((a)[3]), "r"(b0), "r"(b1))

__device__ __forceinline__ uint4 pack8(float4 a, float4 b) {
    __half2 p0 = __floats2half2_rn(a.x, a.y);
    __half2 p1 = __floats2half2_rn(a.z, a.w);
    __half2 p2 = __floats2half2_rn(b.x, b.y);
    __half2 p3 = __floats2half2_rn(b.z, b.w);
    uint4 o;
    o.x = *(uint32_t*)&p0; o.y = *(uint32_t*)&p1;
    o.z = *(uint32_t*)&p2; o.w = *(uint32_t*)&p3;
    return o;
}

__device__ __forceinline__ float blockReduceSum(float v, float* sbuf) {
    #pragma unroll
    for (int o = 16; o > 0; o >>= 1) v += __shfl_down_sync(0xffffffffu, v, o);
    int lane = threadIdx.x & 31, w = threadIdx.x >> 5;
    if (lane == 0) sbuf[w] = v;
    __syncthreads();
    int nw = blockDim.x >> 5;
    v = (threadIdx.x < nw) ? sbuf[threadIdx.x] : 0.f;
    if (w == 0) {
        #pragma unroll
        for (int o = 16; o > 0; o >>= 1) v += __shfl_down_sync(0xffffffffu, v, o);
    }
    if (threadIdx.x == 0) sbuf[0] = v;
    __syncthreads();
    v = sbuf[0];
    __syncthreads();
    return v;
}

// ---------------- 1. layernorm slots ----------------
__global__ void ln_slots_kernel(const float* __restrict__ slots,
                                const float* __restrict__ g,
                                const float* __restrict__ b) {
    __shared__ float sbuf[32];
    int k = blockIdx.x, tid = threadIdx.x;
    float x = slots[k * DIM + tid];
    float mu = blockReduceSum(x, sbuf) * (1.f / DIM);
    float dv = x - mu;
    float var = blockReduceSum(dv * dv, sbuf) * (1.f / DIM);
    d_S[k * DIM + tid] = dv * rsqrtf(var + LN_EPS) * g[tid] + b[tid];
}

// ---------------- 2. fold Q into Wk ----------------
__global__ void fold_kernel(const float* __restrict__ Wk,
                            const float* __restrict__ bk) {
    int rk = blockIdx.x;
    int h = rk >> 6, k = rk & 63;
    __shared__ float sq[HD];
    int tid = threadIdx.x;
    if (tid < HD) sq[tid] = d_S[k * DIM + h * HD + tid];
    __syncthreads();
    for (int j = tid; j < DIM; j += blockDim.x) {
        float acc = 0.f;
        #pragma unroll
        for (int d = 0; d < HD; d++)
            acc = fmaf(sq[d], Wk[(size_t)(h * HD + d) * DIM + j], acc);
        d_Weff[(size_t)rk * DIM + j] = acc * SCALE;
    }
    if (tid == 0) {
        float acc = 0.f;
        #pragma unroll
        for (int d = 0; d < HD; d++) acc += sq[d] * bk[h * HD + d];
        d_beff[rk] = acc * SCALE;
    }
}

// ---------------- 3. merged fp32 -> fp16 conversion ----------------
#define CONVX_BLKS 16384
__global__ void conv_all(const float* __restrict__ X,
                         const float* __restrict__ Wv,
                         const float* __restrict__ bv) {
    if (blockIdx.x < CONVX_BLKS) {
        size_t idx = (size_t)blockIdx.x * 256 + threadIdx.x;
        size_t base = idx * 8;
        float4 a = *(const float4*)&X[base];
        float4 b = *(const float4*)&X[base + 4];
        *(uint4*)&d_Xh[base] = pack8(a, b);
    } else {
        size_t idx = (size_t)(blockIdx.x - CONVX_BLKS) * 256 + threadIdx.x;
        int row = (int)(idx >> 6);
        int c8 = ((int)idx & 63) << 3;
        const float* src = (row < 512) ? &d_Weff[(size_t)row * DIM + c8]
                                       : &Wv[(size_t)(row - 512) * DIM + c8];
        float4 a = *(const float4*)src;
        float4 b = *(const float4*)(src + 4);
        *(uint4*)&d_Wh[(size_t)row * DIM + c8] = pack8(a, b);
        if (c8 == 0) d_bcat[row] = (row < 512) ? d_beff[row] : bv[row - 512];
    }
}

// ---------------- 4. fp16 mma GEMM (256 thr, 2 CTA/SM) + fused softmax ----------------
#define SMD_A(s)     ((s) * 4096)
#define SMD_B(s)     (12288 + (s) * 4096)
#define SMD_BIAS     24576
#define SMEM_BYTES   ((24576 + 128) * 4)

__device__ __forceinline__ void load_chunk(uint32_t sb, const __half* __restrict__ Xh,
                                           const __half* __restrict__ Wh,
                                           int c, int s, int m0, int n0, int tid) {
    int kt = c * KC;
    uint32_t abase = sb + SMD_A(s) * 4;
    uint32_t bbase = sb + SMD_B(s) * 4;
    #pragma unroll
    for (int l = 0; l < 4; l++) {              // A: 128 rows x 8 16B-chunks
        int t = tid + l * 256;
        int r = t >> 3, c8 = t & 7;
        uint32_t dst = abase + SIDX(r, c8 * 4) * 4;
        const __half* src = Xh + (size_t)(m0 + r) * DIM + kt + c8 * 8;
        asm volatile("cp.async.cg.shared.global [%0], [%1], 16;" :: "r"(dst), "l"(src));
    }
    #pragma unroll
    for (int l = 0; l < 4; l++) {              // B: 128 rows x 8 16B-chunks
        int t = tid + l * 256;
        int r = t >> 3, c8 = t & 7;
        uint32_t dst = bbase + SIDX(r, c8 * 4) * 4;
        const __half* src = Wh + (size_t)(n0 + r) * DIM + kt + c8 * 8;
        asm volatile("cp.async.cg.shared.global [%0], [%1], 16;" :: "r"(dst), "l"(src));
    }
    asm volatile("cp.async.commit_group;" ::: "memory");
}

__global__ void __launch_bounds__(256, 2) gemm_fp16(const __half* __restrict__ Xh,
                                                    const __half* __restrict__ Wh,
                                                    const float* __restrict__ bias,
                                                    __half* __restrict__ out) {
    extern __shared__ uint32_t sm32[];
    float* smf = (float*)sm32;
    uint32_t sb = s2u(sm32);
    const int tid = threadIdx.x;
    const int wid = tid >> 5, lane = tid & 31;
    const int g = lane >> 2, tg = lane & 3;
    const int q1 = (lane >> 3) & 1;     // +8-row select
    const int q2 = lane >> 4;           // k-chunk select
    const int wm = (wid & 3) * 32;      // 4 warp rows
    const int wn = (wid >> 2) * 64;     // 2 warp cols
    const int m0 = blockIdx.y * MT;
    const int n0 = blockIdx.x * NT;

    if (tid < NT) smf[SMD_BIAS + tid] = bias[n0 + tid];

    float d[2][8][4];
    #pragma unroll
    for (int mt = 0; mt < 2; mt++)
        #pragma unroll
        for (int nt = 0; nt < 8; nt++)
            #pragma unroll
            for (int i = 0; i < 4; i++) d[mt][nt][i] = 0.f;

    load_chunk(sb, Xh, Wh, 0, 0, m0, n0, tid);
    load_chunk(sb, Xh, Wh, 1, 1, m0, n0, tid);

    for (int c = 0; c < NCHUNK; c++) {
        int s = c % 3;
        if (c + 2 < NCHUNK) load_chunk(sb, Xh, Wh, c + 2, (c + 2) % 3, m0, n0, tid);
        if (c <= NCHUNK - 3)      asm volatile("cp.async.wait_group 2;" ::: "memory");
        else if (c == NCHUNK - 2) asm volatile("cp.async.wait_group 1;" ::: "memory");
        else                      asm volatile("cp.async.wait_group 0;" ::: "memory");
        __syncthreads();

        #pragma unroll
        for (int ks = 0; ks < 4; ks++) {
            int dcol = ks * 8 + q2 * 4;
            uint32_t a[2][4], bfr[8][2];
            #pragma unroll
            for (int mt = 0; mt < 2; mt++) {
                int row = wm + mt * 16 + q1 * 8 + (lane & 7);
                uint32_t ad = sb + (SMD_A(s) + SIDX(row, dcol)) * 4;
                LDSM4(a[mt][0], a[mt][1], a[mt][2], a[mt][3], ad);
            }
            #pragma unroll
            for (int p = 0; p < 4; p++) {
                int row = wn + p * 16 + q1 * 8 + (lane & 7);
                uint32_t bd = sb + (SMD_B(s) + SIDX(row, dcol)) * 4;
                LDSM4(bfr[2*p][0], bfr[2*p+1][0], bfr[2*p][1], bfr[2*p+1][1], bd);
            }
            #pragma unroll
            for (int mt = 0; mt < 2; mt++)
                #pragma unroll
                for (int nt = 0; nt < 8; nt++)
                    MMA16816(d[mt][nt], a[mt], bfr[nt][0], bfr[nt][1]);
        }
        __syncthreads();
    }

    // ---------------- epilogue: all 8 warps tile 128x128 disjointly ----------------
    #pragma unroll
    for (int mt = 0; mt < 2; mt++) {
        int r = wm + mt * 16 + g;
        #pragma unroll
        for (int nt = 0; nt < 8; nt++) {
            int cl = wn + nt * 8 + tg * 2;
            float b0 = smf[SMD_BIAS + cl];
            float b1 = smf[SMD_BIAS + cl + 1];
            float2 v0 = {d[mt][nt][0] + b0, d[mt][nt][1] + b1};
            float2 v1 = {d[mt][nt][2] + b0, d[mt][nt][3] + b1};
            *(float2*)&smf[r * 132 + cl]       = v0;
            *(float2*)&smf[(r + 8) * 132 + cl] = v1;
        }
    }
    __syncthreads();

    if (blockIdx.x < 4) {       // logits region: softmax per 64-col head group
        int r = tid >> 1, hg = tid & 1;
        const float* row = smf + r * 132 + hg * 64;
        float v[64];
        float m = row[0];
        #pragma unroll
        for (int i = 0; i < 64; i++) { v[i] = row[i]; m = fmaxf(m, v[i]); }
        float ssum = 0.f;
        #pragma unroll
        for (int i = 0; i < 64; i++) { v[i] = expf(v[i] - m); ssum += v[i]; }
        float inv = 1.f / ssum;
        __half* op = out + (size_t)(m0 + r) * NTOT + n0 + hg * 64;
        #pragma unroll
        for (int i = 0; i < 64; i += 8) {
            float4 a = {v[i] * inv, v[i+1] * inv, v[i+2] * inv, v[i+3] * inv};
            float4 b = {v[i+4] * inv, v[i+5] * inv, v[i+6] * inv, v[i+7] * inv};
            *(uint4*)(op + i) = pack8(a, b);
        }
    } else {                    // V region: plain fp16 store
        for (int i = tid; i < 128 * 16; i += 256) {
            int r = i >> 4, c8 = (i & 15) * 8;
            float4 a = *(const float4*)&smf[r * 132 + c8];
            float4 b = *(const float4*)&smf[r * 132 + c8 + 4];
            *(uint4*)&out[(size_t)(m0 + r) * NTOT + n0 + c8] = pack8(a, b);
        }
    }
}

// ---------------- 5. zero accumulators ----------------
__global__ void zero_kernel() {
    int i = blockIdx.x * blockDim.x + threadIdx.x;
    if (i < BATCH * DIM * HD) d_Num[i] = 0.f;
    if (i < BATCH * DIM)      d_C[i] = 0.f;
}

// ---------------- 6. tensor-core accum: Num = W^T V, C = colsum(W) ----------------
__device__ __forceinline__ void acc_load(uint32_t wbase, uint32_t vbase,
                                         size_t grow0, int h, int ch, int buf, int tid) {
    #pragma unroll
    for (int l = 0; l < 4; l++) {
        int t = tid + l * 128;
        int r = t >> 3, cc = t & 7;
        size_t ga = (grow0 + (size_t)ch * 64 + r) * NTOT + h * HD + cc * 8;
        uint32_t off = ((uint32_t)buf * 4096 + r * 64 + ((cc ^ (r & 7)) * 8)) * 2;
        asm volatile("cp.async.cg.shared.global [%0], [%1], 16;"
                     :: "r"(wbase + off), "l"(d_LVh + ga));
        asm volatile("cp.async.cg.shared.global [%0], [%1], 16;"
                     :: "r"(vbase + off), "l"(d_LVh + ga + 512));
    }
    asm volatile("cp.async.commit_group;" ::: "memory");
}

__global__ __launch_bounds__(128) void accum_mma() {
    __shared__ __half Wst[2][64 * 64];
    __shared__ __half Vst[2][64 * 64];
    int sc = blockIdx.x, h = blockIdx.y, b = blockIdx.z;
    int tid = threadIdx.x, warp = tid >> 5, lane = tid & 31;
    int q1 = (lane >> 3) & 1, q2 = lane >> 4;
    uint32_t wbase = s2u(Wst), vbase = s2u(Vst);
    size_t grow0 = (size_t)b * SEQ + sc * 1024;

    float acc[8][4];
    #pragma unroll
    for (int nt = 0; nt < 8; nt++)
        #pragma unroll
        for (int i = 0; i < 4; i++) acc[nt][i] = 0.f;
    float cacc0 = 0.f, cacc1 = 0.f;

    acc_load(wbase, vbase, grow0, h, 0, 0, tid);
    for (int ch = 0; ch < 16; ch++) {
        int buf = ch & 1;
        if (ch + 1 < 16) {
            acc_load(wbase, vbase, grow0, h, ch + 1, buf ^ 1, tid);
            asm volatile("cp.async.wait_group 1;" ::: "memory");
        } else {
            asm volatile("cp.async.wait_group 0;" ::: "memory");
        }
        __syncthreads();
        #pragma unroll
        for (int ks = 0; ks < 4; ks++) {
            int s_loc = ks * 16 + q2 * 8 + (lane & 7);
            uint32_t a[4];
            {
                int cc = warp * 2 + q1;
                uint32_t ad = wbase + ((uint32_t)buf * 4096 + s_loc * 64 + ((cc ^ (s_loc & 7)) * 8)) * 2;
                LDSM4T(a[0], a[1], a[2], a[3], ad);
            }
            {   // slot-sum of W from A fragments
                float2 f;
                f = __half22float2(*(__half2*)&a[0]); cacc0 += f.x + f.y;
                f = __half22float2(*(__half2*)&a[2]); cacc0 += f.x + f.y;
                f = __half22float2(*(__half2*)&a[1]); cacc1 += f.x + f.y;
                f = __half22float2(*(__half2*)&a[3]); cacc1 += f.x + f.y;
            }
            #pragma unroll
            for (int p = 0; p < 4; p++) {
                uint32_t r0, r1, r2, r3;
                int cc = p * 2 + q1;
                uint32_t vd = vbase + ((uint32_t)buf * 4096 + s_loc * 64 + ((cc ^ (s_loc & 7)) * 8)) * 2;
                LDSM4T(r0, r1, r2, r3, vd);
                MMA16816(acc[2*p],     a, r0, r2);
                MMA16816(acc[2*p + 1], a, r1, r3);
            }
        }
        __syncthreads();
    }

    cacc0 += __shfl_xor_sync(0xffffffffu, cacc0, 1);
    cacc0 += __shfl_xor_sync(0xffffffffu, cacc0, 2);
    cacc1 += __shfl_xor_sync(0xffffffffu, cacc1, 1);
    cacc1 += __shfl_xor_sync(0xffffffffu, cacc1, 2);
    int slot0 = warp * 16 + (lane >> 2);
    if ((lane & 3) == 0) {
        atomicAdd(&d_C[b * DIM + h * HD + slot0],     cacc0);
        atomicAdd(&d_C[b * DIM + h * HD + slot0 + 8], cacc1);
    }
    #pragma unroll
    for (int nt = 0; nt < 8; nt++) {
        int dc = nt * 8 + (lane & 3) * 2;
        float* p0 = &d_Num[((size_t)b * DIM + h * HD + slot0) * HD + dc];
        float* p1 = &d_Num[((size_t)b * DIM + h * HD + slot0 + 8) * HD + dc];
        atomicAdd(p0,     acc[nt][0]);
        atomicAdd(p0 + 1, acc[nt][1]);
        atomicAdd(p1,     acc[nt][2]);
        atomicAdd(p1 + 1, acc[nt][3]);
    }
}

// ---------------- 7. divide, transpose, final LN ----------------
__global__ void final_kernel(const float* __restrict__ g,
                             const float* __restrict__ bb,
                             float* __restrict__ out) {
    __shared__ float sbuf[32];
    int blk = blockIdx.x;
    int b = blk >> 6, k = blk & 63;
    int tid = threadIdx.x;
    int h = tid >> 6, d = tid & 63;
    float c = d_C[b * DIM + h * HD + k];
    float v = d_Num[((size_t)b * DIM + h * HD + k) * HD + d] / (c + EPS_C);
    float mu = blockReduceSum(v, sbuf) * (1.f / DIM);
    float dv = v - mu;
    float var = blockReduceSum(dv * dv, sbuf) * (1.f / DIM);
    out[(size_t)blk * DIM + tid] = dv * rsqrtf(var + LN_EPS) * g[tid] + bb[tid];
}

// ---------------- launch ----------------
extern "C" void kernel_launch(void* const* d_in, const int* in_sizes, int n_in,
                              void* d_out, int out_size) {
    const float* X       = (const float*)d_in[0];
    const float* slots_w = (const float*)d_in[1];
    const float* g_slots = (const float*)d_in[2];
    const float* b_slots = (const float*)d_in[3];
    const float* Wk      = (const float*)d_in[4];
    const float* bk      = (const float*)d_in[5];
    const float* Wv      = (const float*)d_in[6];
    const float* bv      = (const float*)d_in[7];
    const float* g_after = (const float*)d_in[8];
    const float* b_after = (const float*)d_in[9];
    float* out = (float*)d_out;

    __half *pXh, *pWh, *pLVh;
    float *pbcat;
    cudaGetSymbolAddress((void**)&pXh, d_Xh);
    cudaGetSymbolAddress((void**)&pWh, d_Wh);
    cudaGetSymbolAddress((void**)&pbcat, d_bcat);
    cudaGetSymbolAddress((void**)&pLVh, d_LVh);

    static bool attr_set = false;
    if (!attr_set) {
        cudaFuncSetAttribute(gemm_fp16, cudaFuncAttributeMaxDynamicSharedMemorySize, SMEM_BYTES);
        attr_set = true;
    }

    ln_slots_kernel<<<KSLOTS, DIM>>>(slots_w, g_slots, b_slots);
    fold_kernel<<<DIM, 256>>>(Wk, bk);
    conv_all<<<CONVX_BLKS + 256, 256>>>(X, Wv, bv);

    dim3 ggrid(NTOT / NT, BT / MT);   // (8, 512)
    gemm_fp16<<<ggrid, 256, SMEM_BYTES>>>(pXh, pWh, pbcat, pLVh);

    zero_kernel<<<(BATCH * DIM * HD + 255) / 256, 256>>>();
    accum_mma<<<dim3(8, HEADS, BATCH), 128>>>();
    final_kernel<<<BATCH * KSLOTS, DIM>>>(g_after, b_after, out);
}

// round 12
// speedup vs baseline: 6.2046x; 1.0420x over previous
#include <cuda_runtime.h>
#include <cuda_fp16.h>
#include <cstdint>

#define BATCH   8
#define SEQ     8192
#define BT      65536
#define DIM     512
#define HEADS   8
#define HD      64
#define KSLOTS  64
#define SCALE   0.125f
#define EPS_C   1e-20f
#define LN_EPS  1e-5f

#define NTOT    1024        // [logits(512) | V(512)]
#define MT      128
#define NT      128
#define KC      64          // k-chunk (halves)
#define NCHUNK  8           // 512/64

// ---------------- scratch ----------------
__device__ float d_S[KSLOTS * DIM];
__device__ float d_Weff[DIM * DIM];
__device__ float d_beff[DIM];
__device__ float d_bcat[NTOT];
__device__ __half d_Xh[(size_t)BT * DIM];
__device__ __half d_Wh[(size_t)NTOT * DIM];
__device__ __half d_LVh[(size_t)BT * NTOT];
__device__ float d_Num[BATCH * DIM * HD];
__device__ float d_C[BATCH * DIM];

// ---------------- helpers ----------------
__device__ __forceinline__ uint32_t s2u(const void* p) {
    uint32_t a;
    asm("{ .reg .u64 t; cvta.to.shared.u64 t, %1; cvt.u32.u64 %0, t; }" : "=r"(a) : "l"(p));
    return a;
}
// swizzled dword index within a [rows][32-dword] tile
#define SIDX(r, c) (((r) << 5) + ((c) ^ (((r) & 7) << 2)))

#define LDSM4(r0, r1, r2, r3, addr) \
    asm volatile("ldmatrix.sync.aligned.m8n8.x4.shared.b16 {%0,%1,%2,%3}, [%4];" \
        : "=r"(r0), "=r"(r1), "=r"(r2), "=r"(r3) : "r"(addr))

#define LDSM4T(r0, r1, r2, r3, addr) \
    asm volatile("ldmatrix.sync.aligned.m8n8.x4.trans.shared.b16 {%0,%1,%2,%3}, [%4];" \
        : "=r"(r0), "=r"(r1), "=r"(r2), "=r"(r3) : "r"(addr))

#define MMA16816(d, a, b0, b1) \
    asm volatile( \
        "mma.sync.aligned.m16n8k16.row.col.f32.f16.f16.f32 " \
        "{%0,%1,%2,%3}, {%4,%5,%6,%7}, {%8,%9}, {%0,%1,%2,%3};" \
        : "+f"((d)[0]), "+f"((d)[1]), "+f"((d)[2]), "+f"((d)[3]) \
        : "r"((a)[0]), "r"((a)[1]), "r"((a)[2]), "r"((a)[3]), "r"(b0), "r"(b1))

__device__ __forceinline__ uint4 pack8(float4 a, float4 b) {
    __half2 p0 = __floats2half2_rn(a.x, a.y);
    __half2 p1 = __floats2half2_rn(a.z, a.w);
    __half2 p2 = __floats2half2_rn(b.x, b.y);
    __half2 p3 = __floats2half2_rn(b.z, b.w);
    uint4 o;
    o.x = *(uint32_t*)&p0; o.y = *(uint32_t*)&p1;
    o.z = *(uint32_t*)&p2; o.w = *(uint32_t*)&p3;
    return o;
}

__device__ __forceinline__ float blockReduceSum(float v, float* sbuf) {
    #pragma unroll
    for (int o = 16; o > 0; o >>= 1) v += __shfl_down_sync(0xffffffffu, v, o);
    int lane = threadIdx.x & 31, w = threadIdx.x >> 5;
    if (lane == 0) sbuf[w] = v;
    __syncthreads();
    int nw = blockDim.x >> 5;
    v = (threadIdx.x < nw) ? sbuf[threadIdx.x] : 0.f;
    if (w == 0) {
        #pragma unroll
        for (int o = 16; o > 0; o >>= 1) v += __shfl_down_sync(0xffffffffu, v, o);
    }
    if (threadIdx.x == 0) sbuf[0] = v;
    __syncthreads();
    v = sbuf[0];
    __syncthreads();
    return v;
}

// ---------------- 1. layernorm slots ----------------
__global__ void ln_slots_kernel(const float* __restrict__ slots,
                                const float* __restrict__ g,
                                const float* __restrict__ b) {
    __shared__ float sbuf[32];
    int k = blockIdx.x, tid = threadIdx.x;
    float x = slots[k * DIM + tid];
    float mu = blockReduceSum(x, sbuf) * (1.f / DIM);
    float dv = x - mu;
    float var = blockReduceSum(dv * dv, sbuf) * (1.f / DIM);
    d_S[k * DIM + tid] = dv * rsqrtf(var + LN_EPS) * g[tid] + b[tid];
}

// ---------------- 2. fold Q into Wk ----------------
__global__ void fold_kernel(const float* __restrict__ Wk,
                            const float* __restrict__ bk) {
    int rk = blockIdx.x;
    int h = rk >> 6, k = rk & 63;
    __shared__ float sq[HD];
    int tid = threadIdx.x;
    if (tid < HD) sq[tid] = d_S[k * DIM + h * HD + tid];
    __syncthreads();
    for (int j = tid; j < DIM; j += blockDim.x) {
        float acc = 0.f;
        #pragma unroll
        for (int d = 0; d < HD; d++)
            acc = fmaf(sq[d], Wk[(size_t)(h * HD + d) * DIM + j], acc);
        d_Weff[(size_t)rk * DIM + j] = acc * SCALE;
    }
    if (tid == 0) {
        float acc = 0.f;
        #pragma unroll
        for (int d = 0; d < HD; d++) acc += sq[d] * bk[h * HD + d];
        d_beff[rk] = acc * SCALE;
    }
}

// ---------------- 3. merged fp32 -> fp16 conversion + accumulator zeroing ----------------
#define CONVX_BLKS 16384
#define CONVW_BLKS 256
#define ZERO_BLKS  256
__global__ void conv_all(const float* __restrict__ X,
                         const float* __restrict__ Wv,
                         const float* __restrict__ bv) {
    if (blockIdx.x < CONVX_BLKS) {
        size_t idx = (size_t)blockIdx.x * 256 + threadIdx.x;
        size_t base = idx * 8;
        float4 a = *(const float4*)&X[base];
        float4 b = *(const float4*)&X[base + 4];
        *(uint4*)&d_Xh[base] = pack8(a, b);
    } else if (blockIdx.x < CONVX_BLKS + CONVW_BLKS) {
        size_t idx = (size_t)(blockIdx.x - CONVX_BLKS) * 256 + threadIdx.x;
        int row = (int)(idx >> 6);
        int c8 = ((int)idx & 63) << 3;
        const float* src = (row < 512) ? &d_Weff[(size_t)row * DIM + c8]
                                       : &Wv[(size_t)(row - 512) * DIM + c8];
        float4 a = *(const float4*)src;
        float4 b = *(const float4*)(src + 4);
        *(uint4*)&d_Wh[(size_t)row * DIM + c8] = pack8(a, b);
        if (c8 == 0) d_bcat[row] = (row < 512) ? d_beff[row] : bv[row - 512];
    } else {
        int z = blockIdx.x - CONVX_BLKS - CONVW_BLKS;
        float4 zero4 = {0.f, 0.f, 0.f, 0.f};
        *(float4*)&d_Num[((size_t)z * 256 + threadIdx.x) * 4] = zero4;
        if (z == 0) {
            #pragma unroll
            for (int i = 0; i < 16; i++) d_C[threadIdx.x + i * 256] = 0.f;
        }
    }
}

// ---------------- 4. fp16 mma GEMM (hoisted addressing) + fused softmax ----------------
// byte offsets: A stages s*16384 (3x16KB); B stages 49152 + s*16384; bias @98304
#define SMB_B0       49152
#define SMD_BIAS     24576            // dword index of bias (= byte 98304)
#define SMEM_BYTES   ((24576 + 128) * 4)

__device__ __forceinline__ void load_chunk(uint32_t adst, uint32_t bdst,
                                           const __half* __restrict__ a,
                                           const __half* __restrict__ b) {
    #pragma unroll
    for (int l = 0; l < 4; l++) {
        asm volatile("cp.async.cg.shared.global [%0], [%1], 16;"
                     :: "r"(adst + l * 4096), "l"(a + (size_t)l * 32 * DIM));
        asm volatile("cp.async.cg.shared.global [%0], [%1], 16;"
                     :: "r"(bdst + l * 4096), "l"(b + (size_t)l * 32 * DIM));
    }
    asm volatile("cp.async.commit_group;" ::: "memory");
}

__global__ void __launch_bounds__(256, 2) gemm_fp16(const __half* __restrict__ Xh,
                                                    const __half* __restrict__ Wh,
                                                    const float* __restrict__ bias,
                                                    __half* __restrict__ out) {
    extern __shared__ uint32_t sm32[];
    float* smf = (float*)sm32;
    uint32_t sb = s2u(sm32);
    const int tid = threadIdx.x;
    const int wid = tid >> 5, lane = tid & 31;
    const int g = lane >> 2, tg = lane & 3;
    const int q1 = (lane >> 3) & 1;     // +8-row select
    const int q2 = lane >> 4;           // k-chunk select
    const int wm = (wid & 3) * 32;      // 4 warp rows
    const int wn = (wid >> 2) * 64;     // 2 warp cols
    const int m0 = blockIdx.y * MT;
    const int n0 = blockIdx.x * NT;

    if (tid < NT) smf[SMD_BIAS + tid] = bias[n0 + tid];

    // ---- hoisted loader state (per-thread, chunk-invariant) ----
    const int lr = tid >> 3, lc = tid & 7;
    const __half* aptr = Xh + (size_t)(m0 + lr) * DIM + lc * 8;
    const __half* bptr = Wh + (size_t)(n0 + lr) * DIM + lc * 8;
    const uint32_t ldst = (uint32_t)SIDX(lr, lc * 4) * 4;

    // ---- hoisted fragment offsets (stage 0, ks 0) ----
    const int fr = q1 * 8 + (lane & 7);
    uint32_t aoff[2], boff[4];
    #pragma unroll
    for (int mt = 0; mt < 2; mt++)
        aoff[mt] = (uint32_t)SIDX(wm + mt * 16 + fr, q2 * 4) * 4;
    #pragma unroll
    for (int p = 0; p < 4; p++)
        boff[p] = SMB_B0 + (uint32_t)SIDX(wn + p * 16 + fr, q2 * 4) * 4;

    float d[2][8][4];
    #pragma unroll
    for (int mt = 0; mt < 2; mt++)
        #pragma unroll
        for (int nt = 0; nt < 8; nt++)
            #pragma unroll
            for (int i = 0; i < 4; i++) d[mt][nt][i] = 0.f;

    load_chunk(sb + ldst,         sb + ldst + SMB_B0,         aptr,      bptr);
    load_chunk(sb + ldst + 16384, sb + ldst + SMB_B0 + 16384, aptr + KC, bptr + KC);
    const __half* apf = aptr + 2 * KC;
    const __half* bpf = bptr + 2 * KC;

    int s = 0, spf = 2;
    for (int c = 0; c < NCHUNK; c++) {
        if (c + 2 < NCHUNK) {
            uint32_t d0 = sb + ldst + (uint32_t)spf * 16384;
            load_chunk(d0, d0 + SMB_B0, apf, bpf);
            apf += KC; bpf += KC;
            if (++spf == 3) spf = 0;
        }
        if (c <= NCHUNK - 3)      asm volatile("cp.async.wait_group 2;" ::: "memory");
        else if (c == NCHUNK - 2) asm volatile("cp.async.wait_group 1;" ::: "memory");
        else                      asm volatile("cp.async.wait_group 0;" ::: "memory");
        __syncthreads();

        const uint32_t sbs = sb + (uint32_t)s * 16384;
        #pragma unroll
        for (int ks = 0; ks < 4; ks++) {
            const uint32_t kx = (uint32_t)ks * 32;
            uint32_t a[2][4], bfr[8][2];
            #pragma unroll
            for (int mt = 0; mt < 2; mt++)
                LDSM4(a[mt][0], a[mt][1], a[mt][2], a[mt][3], sbs + (aoff[mt] ^ kx));
            #pragma unroll
            for (int p = 0; p < 4; p++)
                LDSM4(bfr[2*p][0], bfr[2*p+1][0], bfr[2*p][1], bfr[2*p+1][1],
                      sbs + (boff[p] ^ kx));
            #pragma unroll
            for (int mt = 0; mt < 2; mt++)
                #pragma unroll
                for (int nt = 0; nt < 8; nt++)
                    MMA16816(d[mt][nt], a[mt], bfr[nt][0], bfr[nt][1]);
        }
        __syncthreads();
        if (++s == 3) s = 0;
    }

    // ---------------- epilogue: all 8 warps tile 128x128 disjointly ----------------
    #pragma unroll
    for (int mt = 0; mt < 2; mt++) {
        int r = wm + mt * 16 + g;
        #pragma unroll
        for (int nt = 0; nt < 8; nt++) {
            int cl = wn + nt * 8 + tg * 2;
            float b0 = smf[SMD_BIAS + cl];
            float b1 = smf[SMD_BIAS + cl + 1];
            float2 v0 = {d[mt][nt][0] + b0, d[mt][nt][1] + b1};
            float2 v1 = {d[mt][nt][2] + b0, d[mt][nt][3] + b1};
            *(float2*)&smf[r * 132 + cl]       = v0;
            *(float2*)&smf[(r + 8) * 132 + cl] = v1;
        }
    }
    __syncthreads();

    if (blockIdx.x < 4) {       // logits region: softmax per 64-col head group
        int r = tid >> 1, hg = tid & 1;
        const float* row = smf + r * 132 + hg * 64;
        float v[64];
        float m = row[0];
        #pragma unroll
        for (int i = 0; i < 64; i++) { v[i] = row[i]; m = fmaxf(m, v[i]); }
        float ssum = 0.f;
        #pragma unroll
        for (int i = 0; i < 64; i++) { v[i] = expf(v[i] - m); ssum += v[i]; }
        float inv = 1.f / ssum;
        __half* op = out + (size_t)(m0 + r) * NTOT + n0 + hg * 64;
        #pragma unroll
        for (int i = 0; i < 64; i += 8) {
            float4 a = {v[i] * inv, v[i+1] * inv, v[i+2] * inv, v[i+3] * inv};
            float4 b = {v[i+4] * inv, v[i+5] * inv, v[i+6] * inv, v[i+7] * inv};
            *(uint4*)(op + i) = pack8(a, b);
        }
    } else {                    // V region: plain fp16 store
        for (int i = tid; i < 128 * 16; i += 256) {
            int r = i >> 4, c8 = (i & 15) * 8;
            float4 a = *(const float4*)&smf[r * 132 + c8];
            float4 b = *(const float4*)&smf[r * 132 + c8 + 4];
            *(uint4*)&out[(size_t)(m0 + r) * NTOT + n0 + c8] = pack8(a, b);
        }
    }
}

// ---------------- 6. tensor-core accum: Num = W^T V, C = colsum(W) ----------------
__device__ __forceinline__ void acc_load(uint32_t wbase, uint32_t vbase,
                                         size_t grow0, int h, int ch, int buf, int tid) {
    #pragma unroll
    for (int l = 0; l < 4; l++) {
        int t = tid + l * 128;
        int r = t >> 3, cc = t & 7;
        size_t ga = (grow0 + (size_t)ch * 64 + r) * NTOT + h * HD + cc * 8;
        uint32_t off = ((uint32_t)buf * 4096 + r * 64 + ((cc ^ (r & 7)) * 8)) * 2;
        asm volatile("cp.async.cg.shared.global [%0], [%1], 16;"
                     :: "r"(wbase + off), "l"(d_LVh + ga));
        asm volatile("cp.async.cg.shared.global [%0], [%1], 16;"
                     :: "r"(vbase + off), "l"(d_LVh + ga + 512));
    }
    asm volatile("cp.async.commit_group;" ::: "memory");
}

__global__ __launch_bounds__(128) void accum_mma() {
    __shared__ __half Wst[2][64 * 64];
    __shared__ __half Vst[2][64 * 64];
    int sc = blockIdx.x, h = blockIdx.y, b = blockIdx.z;
    int tid = threadIdx.x, warp = tid >> 5, lane = tid & 31;
    int q1 = (lane >> 3) & 1, q2 = lane >> 4;
    uint32_t wbase = s2u(Wst), vbase = s2u(Vst);
    size_t grow0 = (size_t)b * SEQ + sc * 1024;

    float acc[8][4];
    #pragma unroll
    for (int nt = 0; nt < 8; nt++)
        #pragma unroll
        for (int i = 0; i < 4; i++) acc[nt][i] = 0.f;
    float cacc0 = 0.f, cacc1 = 0.f;

    acc_load(wbase, vbase, grow0, h, 0, 0, tid);
    for (int ch = 0; ch < 16; ch++) {
        int buf = ch & 1;
        if (ch + 1 < 16) {
            acc_load(wbase, vbase, grow0, h, ch + 1, buf ^ 1, tid);
            asm volatile("cp.async.wait_group 1;" ::: "memory");
        } else {
            asm volatile("cp.async.wait_group 0;" ::: "memory");
        }
        __syncthreads();
        #pragma unroll
        for (int ks = 0; ks < 4; ks++) {
            int s_loc = ks * 16 + q2 * 8 + (lane & 7);
            uint32_t a[4];
            {
                int cc = warp * 2 + q1;
                uint32_t ad = wbase + ((uint32_t)buf * 4096 + s_loc * 64 + ((cc ^ (s_loc & 7)) * 8)) * 2;
                LDSM4T(a[0], a[1], a[2], a[3], ad);
            }
            {   // slot-sum of W from A fragments
                float2 f;
                f = __half22float2(*(__half2*)&a[0]); cacc0 += f.x + f.y;
                f = __half22float2(*(__half2*)&a[2]); cacc0 += f.x + f.y;
                f = __half22float2(*(__half2*)&a[1]); cacc1 += f.x + f.y;
                f = __half22float2(*(__half2*)&a[3]); cacc1 += f.x + f.y;
            }
            #pragma unroll
            for (int p = 0; p < 4; p++) {
                uint32_t r0, r1, r2, r3;
                int cc = p * 2 + q1;
                uint32_t vd = vbase + ((uint32_t)buf * 4096 + s_loc * 64 + ((cc ^ (s_loc & 7)) * 8)) * 2;
                LDSM4T(r0, r1, r2, r3, vd);
                MMA16816(acc[2*p],     a, r0, r2);
                MMA16816(acc[2*p + 1], a, r1, r3);
            }
        }
        __syncthreads();
    }

    cacc0 += __shfl_xor_sync(0xffffffffu, cacc0, 1);
    cacc0 += __shfl_xor_sync(0xffffffffu, cacc0, 2);
    cacc1 += __shfl_xor_sync(0xffffffffu, cacc1, 1);
    cacc1 += __shfl_xor_sync(0xffffffffu, cacc1, 2);
    int slot0 = warp * 16 + (lane >> 2);
    if ((lane & 3) == 0) {
        atomicAdd(&d_C[b * DIM + h * HD + slot0],     cacc0);
        atomicAdd(&d_C[b * DIM + h * HD + slot0 + 8], cacc1);
    }
    #pragma unroll
    for (int nt = 0; nt < 8; nt++) {
        int dc = nt * 8 + (lane & 3) * 2;
        float* p0 = &d_Num[((size_t)b * DIM + h * HD + slot0) * HD + dc];
        float* p1 = &d_Num[((size_t)b * DIM + h * HD + slot0 + 8) * HD + dc];
        atomicAdd(p0,     acc[nt][0]);
        atomicAdd(p0 + 1, acc[nt][1]);
        atomicAdd(p1,     acc[nt][2]);
        atomicAdd(p1 + 1, acc[nt][3]);
    }
}

// ---------------- 7. divide, transpose, final LN ----------------
__global__ void final_kernel(const float* __restrict__ g,
                             const float* __restrict__ bb,
                             float* __restrict__ out) {
    __shared__ float sbuf[32];
    int blk = blockIdx.x;
    int b = blk >> 6, k = blk & 63;
    int tid = threadIdx.x;
    int h = tid >> 6, d = tid & 63;
    float c = d_C[b * DIM + h * HD + k];
    float v = d_Num[((size_t)b * DIM + h * HD + k) * HD + d] / (c + EPS_C);
    float mu = blockReduceSum(v, sbuf) * (1.f / DIM);
    float dv = v - mu;
    float var = blockReduceSum(dv * dv, sbuf) * (1.f / DIM);
    out[(size_t)blk * DIM + tid] = dv * rsqrtf(var + LN_EPS) * g[tid] + bb[tid];
}

// ---------------- launch ----------------
extern "C" void kernel_launch(void* const* d_in, const int* in_sizes, int n_in,
                              void* d_out, int out_size) {
    const float* X       = (const float*)d_in[0];
    const float* slots_w = (const float*)d_in[1];
    const float* g_slots = (const float*)d_in[2];
    const float* b_slots = (const float*)d_in[3];
    const float* Wk      = (const float*)d_in[4];
    const float* bk      = (const float*)d_in[5];
    const float* Wv      = (const float*)d_in[6];
    const float* bv      = (const float*)d_in[7];
    const float* g_after = (const float*)d_in[8];
    const float* b_after = (const float*)d_in[9];
    float* out = (float*)d_out;

    __half *pXh, *pWh, *pLVh;
    float *pbcat;
    cudaGetSymbolAddress((void**)&pXh, d_Xh);
    cudaGetSymbolAddress((void**)&pWh, d_Wh);
    cudaGetSymbolAddress((void**)&pbcat, d_bcat);
    cudaGetSymbolAddress((void**)&pLVh, d_LVh);

    static bool attr_set = false;
    if (!attr_set) {
        cudaFuncSetAttribute(gemm_fp16, cudaFuncAttributeMaxDynamicSharedMemorySize, SMEM_BYTES);
        attr_set = true;
    }

    ln_slots_kernel<<<KSLOTS, DIM>>>(slots_w, g_slots, b_slots);
    fold_kernel<<<DIM, 256>>>(Wk, bk);
    conv_all<<<CONVX_BLKS + CONVW_BLKS + ZERO_BLKS, 256>>>(X, Wv, bv);

    dim3 ggrid(NTOT / NT, BT / MT);   // (8, 512)
    gemm_fp16<<<ggrid, 256, SMEM_BYTES>>>(pXh, pWh, pbcat, pLVh);

    accum_mma<<<dim3(8, HEADS, BATCH), 128>>>();
    final_kernel<<<BATCH * KSLOTS, DIM>>>(g_after, b_after, out);
}

// round 13
// speedup vs baseline: 6.2621x; 1.0093x over previous
#include <cuda_runtime.h>
#include <cuda_fp16.h>
#include <cstdint>

#define BATCH   8
#define SEQ     8192
#define BT      65536
#define DIM     512
#define HEADS   8
#define HD      64
#define KSLOTS  64
#define SCALE   0.125f
#define EPS_C   1e-20f
#define LN_EPS  1e-5f

#define NTOT    1024        // [logits(512) | V(512)]
#define MT      128
#define NT      128
#define KC      64          // k-chunk (halves)
#define NCHUNK  8           // 512/64

// ---------------- scratch ----------------
__device__ float d_S[KSLOTS * DIM];
__device__ float d_Weff[DIM * DIM];
__device__ float d_beff[DIM];
__device__ float d_bcat[NTOT];
__device__ __half d_Xh[(size_t)BT * DIM];
__device__ __half d_Wh[(size_t)NTOT * DIM];
__device__ __half d_LVh[(size_t)BT * NTOT];
__device__ float d_Num[BATCH * DIM * HD];
__device__ float d_C[BATCH * DIM];

// ---------------- helpers ----------------
__device__ __forceinline__ uint32_t s2u(const void* p) {
    uint32_t a;
    asm("{ .reg .u64 t; cvta.to.shared.u64 t, %1; cvt.u32.u64 %0, t; }" : "=r"(a) : "l"(p));
    return a;
}
// swizzled dword index within a [rows][32-dword] tile
#define SIDX(r, c) (((r) << 5) + ((c) ^ (((r) & 7) << 2)))

#define LDSM4(r0, r1, r2, r3, addr) \
    asm volatile("ldmatrix.sync.aligned.m8n8.x4.shared.b16 {%0,%1,%2,%3}, [%4];" \
        : "=r"(r0), "=r"(r1), "=r"(r2), "=r"(r3) : "r"(addr))

#define LDSM4T(r0, r1, r2, r3, addr) \
    asm volatile("ldmatrix.sync.aligned.m8n8.x4.trans.shared.b16 {%0,%1,%2,%3}, [%4];" \
        : "=r"(r0), "=r"(r1), "=r"(r2), "=r"(r3) : "r"(addr))

#define MMA16816(d, a, b0, b1) \
    asm volatile( \
        "mma.sync.aligned.m16n8k16.row.col.f32.f16.f16.f32 " \
        "{%0,%1,%2,%3}, {%4,%5,%6,%7}, {%8,%9}, {%0,%1,%2,%3};" \
        : "+f"((d)[0]), "+f"((d)[1]), "+f"((d)[2]), "+f"((d)[3]) \
        : "r"((a)[0]), "r"((a)[1]), "r"((a)[2]), "r"((a)[3]), "r"(b0), "r"(b1))

__device__ __forceinline__ uint4 pack8(float4 a, float4 b) {
    __half2 p0 = __floats2half2_rn(a.x, a.y);
    __half2 p1 = __floats2half2_rn(a.z, a.w);
    __half2 p2 = __floats2half2_rn(b.x, b.y);
    __half2 p3 = __floats2half2_rn(b.z, b.w);
    uint4 o;
    o.x = *(uint32_t*)&p0; o.y = *(uint32_t*)&p1;
    o.z = *(uint32_t*)&p2; o.w = *(uint32_t*)&p3;
    return o;
}

__device__ __forceinline__ float blockReduceSum(float v, float* sbuf) {
    #pragma unroll
    for (int o = 16; o > 0; o >>= 1) v += __shfl_down_sync(0xffffffffu, v, o);
    int lane = threadIdx.x & 31, w = threadIdx.x >> 5;
    if (lane == 0) sbuf[w] = v;
    __syncthreads();
    int nw = blockDim.x >> 5;
    v = (threadIdx.x < nw) ? sbuf[threadIdx.x] : 0.f;
    if (w == 0) {
        #pragma unroll
        for (int o = 16; o > 0; o >>= 1) v += __shfl_down_sync(0xffffffffu, v, o);
    }
    if (threadIdx.x == 0) sbuf[0] = v;
    __syncthreads();
    v = sbuf[0];
    __syncthreads();
    return v;
}

// ---------------- 1. layernorm slots ----------------
__global__ void ln_slots_kernel(const float* __restrict__ slots,
                                const float* __restrict__ g,
                                const float* __restrict__ b) {
    __shared__ float sbuf[32];
    int k = blockIdx.x, tid = threadIdx.x;
    float x = slots[k * DIM + tid];
    float mu = blockReduceSum(x, sbuf) * (1.f / DIM);
    float dv = x - mu;
    float var = blockReduceSum(dv * dv, sbuf) * (1.f / DIM);
    d_S[k * DIM + tid] = dv * rsqrtf(var + LN_EPS) * g[tid] + b[tid];
}

// ---------------- 2. fold Q into Wk ----------------
__global__ void fold_kernel(const float* __restrict__ Wk,
                            const float* __restrict__ bk) {
    int rk = blockIdx.x;
    int h = rk >> 6, k = rk & 63;
    __shared__ float sq[HD];
    int tid = threadIdx.x;
    if (tid < HD) sq[tid] = d_S[k * DIM + h * HD + tid];
    __syncthreads();
    for (int j = tid; j < DIM; j += blockDim.x) {
        float acc = 0.f;
        #pragma unroll
        for (int d = 0; d < HD; d++)
            acc = fmaf(sq[d], Wk[(size_t)(h * HD + d) * DIM + j], acc);
        d_Weff[(size_t)rk * DIM + j] = acc * SCALE;
    }
    if (tid == 0) {
        float acc = 0.f;
        #pragma unroll
        for (int d = 0; d < HD; d++) acc += sq[d] * bk[h * HD + d];
        d_beff[rk] = acc * SCALE;
    }
}

// ---------------- 3. merged fp32 -> fp16 conversion + accumulator zeroing ----------------
#define CONVX_BLKS 16384
#define CONVW_BLKS 256
#define ZERO_BLKS  256
__global__ void conv_all(const float* __restrict__ X,
                         const float* __restrict__ Wv,
                         const float* __restrict__ bv) {
    if (blockIdx.x < CONVX_BLKS) {
        size_t idx = (size_t)blockIdx.x * 256 + threadIdx.x;
        size_t base = idx * 8;
        float4 a = *(const float4*)&X[base];
        float4 b = *(const float4*)&X[base + 4];
        *(uint4*)&d_Xh[base] = pack8(a, b);
    } else if (blockIdx.x < CONVX_BLKS + CONVW_BLKS) {
        size_t idx = (size_t)(blockIdx.x - CONVX_BLKS) * 256 + threadIdx.x;
        int row = (int)(idx >> 6);
        int c8 = ((int)idx & 63) << 3;
        const float* src = (row < 512) ? &d_Weff[(size_t)row * DIM + c8]
                                       : &Wv[(size_t)(row - 512) * DIM + c8];
        float4 a = *(const float4*)src;
        float4 b = *(const float4*)(src + 4);
        *(uint4*)&d_Wh[(size_t)row * DIM + c8] = pack8(a, b);
        if (c8 == 0) d_bcat[row] = (row < 512) ? d_beff[row] : bv[row - 512];
    } else {
        int z = blockIdx.x - CONVX_BLKS - CONVW_BLKS;
        float4 zero4 = {0.f, 0.f, 0.f, 0.f};
        *(float4*)&d_Num[((size_t)z * 256 + threadIdx.x) * 4] = zero4;
        if (z == 0) {
            #pragma unroll
            for (int i = 0; i < 16; i++) d_C[threadIdx.x + i * 256] = 0.f;
        }
    }
}

// ---------------- 4. fp16 mma GEMM (zero-ALU mainloop) + fused softmax ----------------
// byte offsets: A stages s*16384 (3x16KB); B stages 49152 + s*16384; bias @98304
#define SMB_B0       49152
#define SMD_BIAS     24576            // dword index of bias (= byte 98304)
#define SMEM_BYTES   ((24576 + 128) * 4)

__device__ __forceinline__ void load_chunk(uint32_t adst, uint32_t bdst,
                                           const __half* __restrict__ a,
                                           const __half* __restrict__ b) {
    #pragma unroll
    for (int l = 0; l < 4; l++) {
        asm volatile("cp.async.cg.shared.global [%0], [%1], 16;"
                     :: "r"(adst + l * 4096), "l"(a + (size_t)l * 32 * DIM));
        asm volatile("cp.async.cg.shared.global [%0], [%1], 16;"
                     :: "r"(bdst + l * 4096), "l"(b + (size_t)l * 32 * DIM));
    }
    asm volatile("cp.async.commit_group;" ::: "memory");
}

__global__ void __launch_bounds__(256, 2) gemm_fp16(const __half* __restrict__ Xh,
                                                    const __half* __restrict__ Wh,
                                                    const float* __restrict__ bias,
                                                    __half* __restrict__ out) {
    extern __shared__ uint32_t sm32[];
    float* smf = (float*)sm32;
    uint32_t sb = s2u(sm32);
    const int tid = threadIdx.x;
    const int wid = tid >> 5, lane = tid & 31;
    const int g = lane >> 2, tg = lane & 3;
    const int q1 = (lane >> 3) & 1;     // +8-row select
    const int q2 = lane >> 4;           // k-chunk select
    const int wm = (wid & 3) * 32;      // 4 warp rows
    const int wn = (wid >> 2) * 64;     // 2 warp cols
    const int m0 = blockIdx.y * MT;
    const int n0 = blockIdx.x * NT;

    if (tid < NT) smf[SMD_BIAS + tid] = bias[n0 + tid];

    // ---- hoisted loader state (per-thread, chunk-invariant) ----
    const int lr = tid >> 3, lc = tid & 7;
    const __half* aptr = Xh + (size_t)(m0 + lr) * DIM + lc * 8;
    const __half* bptr = Wh + (size_t)(n0 + lr) * DIM + lc * 8;
    const uint32_t ldst = (uint32_t)SIDX(lr, lc * 4) * 4;

    // ---- fully precomputed fragment addresses: 24 regs, zero mainloop ALU ----
    const int fr = q1 * 8 + (lane & 7);
    uint32_t aadr[2][4], badr[4][4];
    #pragma unroll
    for (int mt = 0; mt < 2; mt++) {
        uint32_t off = (uint32_t)SIDX(wm + mt * 16 + fr, q2 * 4) * 4;
        #pragma unroll
        for (int ks = 0; ks < 4; ks++)
            aadr[mt][ks] = sb + (off ^ (uint32_t)(ks * 32));
    }
    #pragma unroll
    for (int p = 0; p < 4; p++) {
        uint32_t off = (uint32_t)SIDX(wn + p * 16 + fr, q2 * 4) * 4;
        #pragma unroll
        for (int ks = 0; ks < 4; ks++)
            badr[p][ks] = sb + SMB_B0 + (off ^ (uint32_t)(ks * 32));
    }

    float d[2][8][4];
    #pragma unroll
    for (int mt = 0; mt < 2; mt++)
        #pragma unroll
        for (int nt = 0; nt < 8; nt++)
            #pragma unroll
            for (int i = 0; i < 4; i++) d[mt][nt][i] = 0.f;

    load_chunk(sb + ldst,         sb + ldst + SMB_B0,         aptr,      bptr);
    load_chunk(sb + ldst + 16384, sb + ldst + SMB_B0 + 16384, aptr + KC, bptr + KC);

    #pragma unroll
    for (int c = 0; c < NCHUNK; c++) {
        const int s = c % 3;                       // compile-time after unroll
        if (c + 2 < NCHUNK) {
            const int sp = (c + 2) % 3;
            load_chunk(sb + ldst + sp * 16384, sb + ldst + SMB_B0 + sp * 16384,
                       aptr + (c + 2) * KC, bptr + (c + 2) * KC);
        }
        if (c < NCHUNK - 2)       asm volatile("cp.async.wait_group 2;" ::: "memory");
        else if (c == NCHUNK - 2) asm volatile("cp.async.wait_group 1;" ::: "memory");
        else                      asm volatile("cp.async.wait_group 0;" ::: "memory");
        __syncthreads();

        const uint32_t simm = (uint32_t)(s * 16384);
        #pragma unroll
        for (int ks = 0; ks < 4; ks++) {
            uint32_t a[2][4], bfr[8][2];
            #pragma unroll
            for (int mt = 0; mt < 2; mt++)
                LDSM4(a[mt][0], a[mt][1], a[mt][2], a[mt][3], aadr[mt][ks] + simm);
            #pragma unroll
            for (int p = 0; p < 4; p++)
                LDSM4(bfr[2*p][0], bfr[2*p+1][0], bfr[2*p][1], bfr[2*p+1][1],
                      badr[p][ks] + simm);
            #pragma unroll
            for (int mt = 0; mt < 2; mt++)
                #pragma unroll
                for (int nt = 0; nt < 8; nt++)
                    MMA16816(d[mt][nt], a[mt], bfr[nt][0], bfr[nt][1]);
        }
        __syncthreads();
    }

    // ---------------- epilogue: all 8 warps tile 128x128 disjointly ----------------
    #pragma unroll
    for (int mt = 0; mt < 2; mt++) {
        int r = wm + mt * 16 + g;
        #pragma unroll
        for (int nt = 0; nt < 8; nt++) {
            int cl = wn + nt * 8 + tg * 2;
            float b0 = smf[SMD_BIAS + cl];
            float b1 = smf[SMD_BIAS + cl + 1];
            float2 v0 = {d[mt][nt][0] + b0, d[mt][nt][1] + b1};
            float2 v1 = {d[mt][nt][2] + b0, d[mt][nt][3] + b1};
            *(float2*)&smf[r * 132 + cl]       = v0;
            *(float2*)&smf[(r + 8) * 132 + cl] = v1;
        }
    }
    __syncthreads();

    if (blockIdx.x < 4) {       // logits region: softmax per 64-col head group
        int r = tid >> 1, hg = tid & 1;
        const float* row = smf + r * 132 + hg * 64;
        float v[64];
        float m = row[0];
        #pragma unroll
        for (int i = 0; i < 64; i++) { v[i] = row[i]; m = fmaxf(m, v[i]); }
        float ssum = 0.f;
        #pragma unroll
        for (int i = 0; i < 64; i++) { v[i] = expf(v[i] - m); ssum += v[i]; }
        float inv = 1.f / ssum;
        __half* op = out + (size_t)(m0 + r) * NTOT + n0 + hg * 64;
        #pragma unroll
        for (int i = 0; i < 64; i += 8) {
            float4 a = {v[i] * inv, v[i+1] * inv, v[i+2] * inv, v[i+3] * inv};
            float4 b = {v[i+4] * inv, v[i+5] * inv, v[i+6] * inv, v[i+7] * inv};
            *(uint4*)(op + i) = pack8(a, b);
        }
    } else {                    // V region: plain fp16 store
        for (int i = tid; i < 128 * 16; i += 256) {
            int r = i >> 4, c8 = (i & 15) * 8;
            float4 a = *(const float4*)&smf[r * 132 + c8];
            float4 b = *(const float4*)&smf[r * 132 + c8 + 4];
            *(uint4*)&out[(size_t)(m0 + r) * NTOT + n0 + c8] = pack8(a, b);
        }
    }
}

// ---------------- 6. tensor-core accum: Num = W^T V, C = colsum(W) ----------------
__device__ __forceinline__ void acc_load(uint32_t wbase, uint32_t vbase,
                                         size_t grow0, int h, int ch, int buf, int tid) {
    #pragma unroll
    for (int l = 0; l < 4; l++) {
        int t = tid + l * 128;
        int r = t >> 3, cc = t & 7;
        size_t ga = (grow0 + (size_t)ch * 64 + r) * NTOT + h * HD + cc * 8;
        uint32_t off = ((uint32_t)buf * 4096 + r * 64 + ((cc ^ (r & 7)) * 8)) * 2;
        asm volatile("cp.async.cg.shared.global [%0], [%1], 16;"
                     :: "r"(wbase + off), "l"(d_LVh + ga));
        asm volatile("cp.async.cg.shared.global [%0], [%1], 16;"
                     :: "r"(vbase + off), "l"(d_LVh + ga + 512));
    }
    asm volatile("cp.async.commit_group;" ::: "memory");
}

__global__ __launch_bounds__(128) void accum_mma() {
    __shared__ __half Wst[2][64 * 64];
    __shared__ __half Vst[2][64 * 64];
    int sc = blockIdx.x, h = blockIdx.y, b = blockIdx.z;
    int tid = threadIdx.x, warp = tid >> 5, lane = tid & 31;
    int q1 = (lane >> 3) & 1, q2 = lane >> 4;
    uint32_t wbase = s2u(Wst), vbase = s2u(Vst);
    size_t grow0 = (size_t)b * SEQ + sc * 1024;

    float acc[8][4];
    #pragma unroll
    for (int nt = 0; nt < 8; nt++)
        #pragma unroll
        for (int i = 0; i < 4; i++) acc[nt][i] = 0.f;
    float cacc0 = 0.f, cacc1 = 0.f;

    acc_load(wbase, vbase, grow0, h, 0, 0, tid);
    for (int ch = 0; ch < 16; ch++) {
        int buf = ch & 1;
        if (ch + 1 < 16) {
            acc_load(wbase, vbase, grow0, h, ch + 1, buf ^ 1, tid);
            asm volatile("cp.async.wait_group 1;" ::: "memory");
        } else {
            asm volatile("cp.async.wait_group 0;" ::: "memory");
        }
        __syncthreads();
        #pragma unroll
        for (int ks = 0; ks < 4; ks++) {
            int s_loc = ks * 16 + q2 * 8 + (lane & 7);
            uint32_t a[4];
            {
                int cc = warp * 2 + q1;
                uint32_t ad = wbase + ((uint32_t)buf * 4096 + s_loc * 64 + ((cc ^ (s_loc & 7)) * 8)) * 2;
                LDSM4T(a[0], a[1], a[2], a[3], ad);
            }
            {   // slot-sum of W from A fragments
                float2 f;
                f = __half22float2(*(__half2*)&a[0]); cacc0 += f.x + f.y;
                f = __half22float2(*(__half2*)&a[2]); cacc0 += f.x + f.y;
                f = __half22float2(*(__half2*)&a[1]); cacc1 += f.x + f.y;
                f = __half22float2(*(__half2*)&a[3]); cacc1 += f.x + f.y;
            }
            #pragma unroll
            for (int p = 0; p < 4; p++) {
                uint32_t r0, r1, r2, r3;
                int cc = p * 2 + q1;
                uint32_t vd = vbase + ((uint32_t)buf * 4096 + s_loc * 64 + ((cc ^ (s_loc & 7)) * 8)) * 2;
                LDSM4T(r0, r1, r2, r3, vd);
                MMA16816(acc[2*p],     a, r0, r2);
                MMA16816(acc[2*p + 1], a, r1, r3);
            }
        }
        __syncthreads();
    }

    cacc0 += __shfl_xor_sync(0xffffffffu, cacc0, 1);
    cacc0 += __shfl_xor_sync(0xffffffffu, cacc0, 2);
    cacc1 += __shfl_xor_sync(0xffffffffu, cacc1, 1);
    cacc1 += __shfl_xor_sync(0xffffffffu, cacc1, 2);
    int slot0 = warp * 16 + (lane >> 2);
    if ((lane & 3) == 0) {
        atomicAdd(&d_C[b * DIM + h * HD + slot0],     cacc0);
        atomicAdd(&d_C[b * DIM + h * HD + slot0 + 8], cacc1);
    }
    #pragma unroll
    for (int nt = 0; nt < 8; nt++) {
        int dc = nt * 8 + (lane & 3) * 2;
        float* p0 = &d_Num[((size_t)b * DIM + h * HD + slot0) * HD + dc];
        float* p1 = &d_Num[((size_t)b * DIM + h * HD + slot0 + 8) * HD + dc];
        atomicAdd(p0,     acc[nt][0]);
        atomicAdd(p0 + 1, acc[nt][1]);
        atomicAdd(p1,     acc[nt][2]);
        atomicAdd(p1 + 1, acc[nt][3]);
    }
}

// ---------------- 7. divide, transpose, final LN ----------------
__global__ void final_kernel(const float* __restrict__ g,
                             const float* __restrict__ bb,
                             float* __restrict__ out) {
    __shared__ float sbuf[32];
    int blk = blockIdx.x;
    int b = blk >> 6, k = blk & 63;
    int tid = threadIdx.x;
    int h = tid >> 6, d = tid & 63;
    float c = d_C[b * DIM + h * HD + k];
    float v = d_Num[((size_t)b * DIM + h * HD + k) * HD + d] / (c + EPS_C);
    float mu = blockReduceSum(v, sbuf) * (1.f / DIM);
    float dv = v - mu;
    float var = blockReduceSum(dv * dv, sbuf) * (1.f / DIM);
    out[(size_t)blk * DIM + tid] = dv * rsqrtf(var + LN_EPS) * g[tid] + bb[tid];
}

// ---------------- launch ----------------
extern "C" void kernel_launch(void* const* d_in, const int* in_sizes, int n_in,
                              void* d_out, int out_size) {
    const float* X       = (const float*)d_in[0];
    const float* slots_w = (const float*)d_in[1];
    const float* g_slots = (const float*)d_in[2];
    const float* b_slots = (const float*)d_in[3];
    const float* Wk      = (const float*)d_in[4];
    const float* bk      = (const float*)d_in[5];
    const float* Wv      = (const float*)d_in[6];
    const float* bv      = (const float*)d_in[7];
    const float* g_after = (const float*)d_in[8];
    const float* b_after = (const float*)d_in[9];
    float* out = (float*)d_out;

    __half *pXh, *pWh, *pLVh;
    float *pbcat;
    cudaGetSymbolAddress((void**)&pXh, d_Xh);
    cudaGetSymbolAddress((void**)&pWh, d_Wh);
    cudaGetSymbolAddress((void**)&pbcat, d_bcat);
    cudaGetSymbolAddress((void**)&pLVh, d_LVh);

    static bool attr_set = false;
    if (!attr_set) {
        cudaFuncSetAttribute(gemm_fp16, cudaFuncAttributeMaxDynamicSharedMemorySize, SMEM_BYTES);
        attr_set = true;
    }

    ln_slots_kernel<<<KSLOTS, DIM>>>(slots_w, g_slots, b_slots);
    fold_kernel<<<DIM, 256>>>(Wk, bk);
    conv_all<<<CONVX_BLKS + CONVW_BLKS + ZERO_BLKS, 256>>>(X, Wv, bv);

    dim3 ggrid(NTOT / NT, BT / MT);   // (8, 512)
    gemm_fp16<<<ggrid, 256, SMEM_BYTES>>>(pXh, pWh, pbcat, pLVh);

    accum_mma<<<dim3(8, HEADS, BATCH), 128>>>();
    final_kernel<<<BATCH * KSLOTS, DIM>>>(g_after, b_after, out);
}

// round 14
// speedup vs baseline: 6.4205x; 1.0253x over previous
#include <cuda_runtime.h>
#include <cuda_fp16.h>
#include <cstdint>

#define BATCH   8
#define SEQ     8192
#define BT      65536
#define DIM     512
#define HEADS   8
#define HD      64
#define KSLOTS  64
#define SCALE   0.125f
#define EPS_C   1e-20f
#define LN_EPS  1e-5f

#define NTOT    1024        // [logits(512) | V(512)]
#define MT      128
#define NT      128
#define KC      64          // k-chunk (halves)
#define NCHUNK  8           // 512/64

// ---------------- scratch ----------------
__device__ float d_S[KSLOTS * DIM];
__device__ float d_Weff[DIM * DIM];
__device__ float d_beff[DIM];
__device__ float d_bcat[NTOT];
__device__ __half d_Xh[(size_t)BT * DIM];
__device__ __half d_Wh[(size_t)NTOT * DIM];
__device__ __half d_LVh[(size_t)BT * NTOT];
__device__ float d_Num[BATCH * DIM * HD];
__device__ float d_C[BATCH * DIM];

// ---------------- helpers ----------------
__device__ __forceinline__ uint32_t s2u(const void* p) {
    uint32_t a;
    asm("{ .reg .u64 t; cvta.to.shared.u64 t, %1; cvt.u32.u64 %0, t; }" : "=r"(a) : "l"(p));
    return a;
}
// swizzled dword index within a [rows][32-dword] tile
#define SIDX(r, c) (((r) << 5) + ((c) ^ (((r) & 7) << 2)))

#define LDSM4(r0, r1, r2, r3, addr) \
    asm volatile("ldmatrix.sync.aligned.m8n8.x4.shared.b16 {%0,%1,%2,%3}, [%4];" \
        : "=r"(r0), "=r"(r1), "=r"(r2), "=r"(r3) : "r"(addr))

#define LDSM4T(r0, r1, r2, r3, addr) \
    asm volatile("ldmatrix.sync.aligned.m8n8.x4.trans.shared.b16 {%0,%1,%2,%3}, [%4];" \
        : "=r"(r0), "=r"(r1), "=r"(r2), "=r"(r3) : "r"(addr))

#define MMA16816(d, a, b0, b1) \
    asm volatile( \
        "mma.sync.aligned.m16n8k16.row.col.f32.f16.f16.f32 " \
        "{%0,%1,%2,%3}, {%4,%5,%6,%7}, {%8,%9}, {%0,%1,%2,%3};" \
        : "+f"((d)[0]), "+f"((d)[1]), "+f"((d)[2]), "+f"((d)[3]) \
        : "r"((a)[0]), "r"((a)[1]), "r"((a)[2]), "r"((a)[3]), "r"(b0), "r"(b1))

__device__ __forceinline__ uint4 pack8(float4 a, float4 b) {
    __half2 p0 = __floats2half2_rn(a.x, a.y);
    __half2 p1 = __floats2half2_rn(a.z, a.w);
    __half2 p2 = __floats2half2_rn(b.x, b.y);
    __half2 p3 = __floats2half2_rn(b.z, b.w);
    uint4 o;
    o.x = *(uint32_t*)&p0; o.y = *(uint32_t*)&p1;
    o.z = *(uint32_t*)&p2; o.w = *(uint32_t*)&p3;
    return o;
}

__device__ __forceinline__ float blockReduceSum(float v, float* sbuf) {
    #pragma unroll
    for (int o = 16; o > 0; o >>= 1) v += __shfl_down_sync(0xffffffffu, v, o);
    int lane = threadIdx.x & 31, w = threadIdx.x >> 5;
    if (lane == 0) sbuf[w] = v;
    __syncthreads();
    int nw = blockDim.x >> 5;
    v = (threadIdx.x < nw) ? sbuf[threadIdx.x] : 0.f;
    if (w == 0) {
        #pragma unroll
        for (int o = 16; o > 0; o >>= 1) v += __shfl_down_sync(0xffffffffu, v, o);
    }
    if (threadIdx.x == 0) sbuf[0] = v;
    __syncthreads();
    v = sbuf[0];
    __syncthreads();
    return v;
}

// ---------------- 1. layernorm slots ----------------
__global__ void ln_slots_kernel(const float* __restrict__ slots,
                                const float* __restrict__ g,
                                const float* __restrict__ b) {
    __shared__ float sbuf[32];
    int k = blockIdx.x, tid = threadIdx.x;
    float x = slots[k * DIM + tid];
    float mu = blockReduceSum(x, sbuf) * (1.f / DIM);
    float dv = x - mu;
    float var = blockReduceSum(dv * dv, sbuf) * (1.f / DIM);
    d_S[k * DIM + tid] = dv * rsqrtf(var + LN_EPS) * g[tid] + b[tid];
}

// ---------------- 2. fold Q into Wk ----------------
__global__ void fold_kernel(const float* __restrict__ Wk,
                            const float* __restrict__ bk) {
    int rk = blockIdx.x;
    int h = rk >> 6, k = rk & 63;
    __shared__ float sq[HD];
    int tid = threadIdx.x;
    if (tid < HD) sq[tid] = d_S[k * DIM + h * HD + tid];
    __syncthreads();
    for (int j = tid; j < DIM; j += blockDim.x) {
        float acc = 0.f;
        #pragma unroll
        for (int d = 0; d < HD; d++)
            acc = fmaf(sq[d], Wk[(size_t)(h * HD + d) * DIM + j], acc);
        d_Weff[(size_t)rk * DIM + j] = acc * SCALE;
    }
    if (tid == 0) {
        float acc = 0.f;
        #pragma unroll
        for (int d = 0; d < HD; d++) acc += sq[d] * bk[h * HD + d];
        d_beff[rk] = acc * SCALE;
    }
}

// ---------------- 3. merged fp32 -> fp16 conversion + accumulator zeroing ----------------
#define CONVX_BLKS 16384
#define CONVW_BLKS 256
#define ZERO_BLKS  256
__global__ void conv_all(const float* __restrict__ X,
                         const float* __restrict__ Wv,
                         const float* __restrict__ bv) {
    if (blockIdx.x < CONVX_BLKS) {
        size_t idx = (size_t)blockIdx.x * 256 + threadIdx.x;
        size_t base = idx * 8;
        float4 a = *(const float4*)&X[base];
        float4 b = *(const float4*)&X[base + 4];
        *(uint4*)&d_Xh[base] = pack8(a, b);
    } else if (blockIdx.x < CONVX_BLKS + CONVW_BLKS) {
        size_t idx = (size_t)(blockIdx.x - CONVX_BLKS) * 256 + threadIdx.x;
        int row = (int)(idx >> 6);
        int c8 = ((int)idx & 63) << 3;
        const float* src = (row < 512) ? &d_Weff[(size_t)row * DIM + c8]
                                       : &Wv[(size_t)(row - 512) * DIM + c8];
        float4 a = *(const float4*)src;
        float4 b = *(const float4*)(src + 4);
        *(uint4*)&d_Wh[(size_t)row * DIM + c8] = pack8(a, b);
        if (c8 == 0) d_bcat[row] = (row < 512) ? d_beff[row] : bv[row - 512];
    } else {
        int z = blockIdx.x - CONVX_BLKS - CONVW_BLKS;
        float4 zero4 = {0.f, 0.f, 0.f, 0.f};
        *(float4*)&d_Num[((size_t)z * 256 + threadIdx.x) * 4] = zero4;
        if (z == 0) {
            #pragma unroll
            for (int i = 0; i < 16; i++) d_C[threadIdx.x + i * 256] = 0.f;
        }
    }
}

// ---------------- 4. fp16 mma GEMM (single-barrier pipeline) + fused softmax ----------------
// byte offsets: A stages s*16384 (3x16KB); B stages 49152 + s*16384; bias @98304
#define SMB_B0       49152
#define SMD_BIAS     24576            // dword index of bias (= byte 98304)
#define SMEM_BYTES   ((24576 + 128) * 4)

__device__ __forceinline__ void load_chunk(uint32_t adst, uint32_t bdst,
                                           const __half* __restrict__ a,
                                           const __half* __restrict__ b) {
    #pragma unroll
    for (int l = 0; l < 4; l++) {
        asm volatile("cp.async.cg.shared.global [%0], [%1], 16;"
                     :: "r"(adst + l * 4096), "l"(a + (size_t)l * 32 * DIM));
        asm volatile("cp.async.cg.shared.global [%0], [%1], 16;"
                     :: "r"(bdst + l * 4096), "l"(b + (size_t)l * 32 * DIM));
    }
    asm volatile("cp.async.commit_group;" ::: "memory");
}

__global__ void __launch_bounds__(256, 2) gemm_fp16(const __half* __restrict__ Xh,
                                                    const __half* __restrict__ Wh,
                                                    const float* __restrict__ bias,
                                                    __half* __restrict__ out) {
    extern __shared__ uint32_t sm32[];
    float* smf = (float*)sm32;
    uint32_t sb = s2u(sm32);
    const int tid = threadIdx.x;
    const int wid = tid >> 5, lane = tid & 31;
    const int g = lane >> 2, tg = lane & 3;
    const int q1 = (lane >> 3) & 1;     // +8-row select
    const int q2 = lane >> 4;           // k-chunk select
    const int wm = (wid & 3) * 32;      // 4 warp rows
    const int wn = (wid >> 2) * 64;     // 2 warp cols
    const int m0 = blockIdx.y * MT;
    const int n0 = blockIdx.x * NT;

    if (tid < NT) smf[SMD_BIAS + tid] = bias[n0 + tid];

    // ---- hoisted loader state (per-thread, chunk-invariant) ----
    const int lr = tid >> 3, lc = tid & 7;
    const __half* aptr = Xh + (size_t)(m0 + lr) * DIM + lc * 8;
    const __half* bptr = Wh + (size_t)(n0 + lr) * DIM + lc * 8;
    const uint32_t ldst = (uint32_t)SIDX(lr, lc * 4) * 4;

    // ---- fully precomputed fragment addresses ----
    const int fr = q1 * 8 + (lane & 7);
    uint32_t aadr[2][4], badr[4][4];
    #pragma unroll
    for (int mt = 0; mt < 2; mt++) {
        uint32_t off = (uint32_t)SIDX(wm + mt * 16 + fr, q2 * 4) * 4;
        #pragma unroll
        for (int ks = 0; ks < 4; ks++)
            aadr[mt][ks] = sb + (off ^ (uint32_t)(ks * 32));
    }
    #pragma unroll
    for (int p = 0; p < 4; p++) {
        uint32_t off = (uint32_t)SIDX(wn + p * 16 + fr, q2 * 4) * 4;
        #pragma unroll
        for (int ks = 0; ks < 4; ks++)
            badr[p][ks] = sb + SMB_B0 + (off ^ (uint32_t)(ks * 32));
    }

    float d[2][8][4];
    #pragma unroll
    for (int mt = 0; mt < 2; mt++)
        #pragma unroll
        for (int nt = 0; nt < 8; nt++)
            #pragma unroll
            for (int i = 0; i < 4; i++) d[mt][nt][i] = 0.f;

    load_chunk(sb + ldst,         sb + ldst + SMB_B0,         aptr,      bptr);
    load_chunk(sb + ldst + 16384, sb + ldst + SMB_B0 + 16384, aptr + KC, bptr + KC);

    // single barrier per chunk: wait -> sync -> issue next load -> compute
    #pragma unroll
    for (int c = 0; c < NCHUNK; c++) {
        const int s = c % 3;                       // compile-time after unroll
        if (c < NCHUNK - 1) asm volatile("cp.async.wait_group 1;" ::: "memory");
        else                asm volatile("cp.async.wait_group 0;" ::: "memory");
        __syncthreads();
        if (c + 2 < NCHUNK) {
            const int sp = (c + 2) % 3;            // == (c-1)%3: compute done pre-barrier
            load_chunk(sb + ldst + sp * 16384, sb + ldst + SMB_B0 + sp * 16384,
                       aptr + (c + 2) * KC, bptr + (c + 2) * KC);
        }

        const uint32_t simm = (uint32_t)(s * 16384);
        #pragma unroll
        for (int ks = 0; ks < 4; ks++) {
            uint32_t a[2][4], bfr[8][2];
            #pragma unroll
            for (int mt = 0; mt < 2; mt++)
                LDSM4(a[mt][0], a[mt][1], a[mt][2], a[mt][3], aadr[mt][ks] + simm);
            #pragma unroll
            for (int p = 0; p < 4; p++)
                LDSM4(bfr[2*p][0], bfr[2*p+1][0], bfr[2*p][1], bfr[2*p+1][1],
                      badr[p][ks] + simm);
            #pragma unroll
            for (int mt = 0; mt < 2; mt++)
                #pragma unroll
                for (int nt = 0; nt < 8; nt++)
                    MMA16816(d[mt][nt], a[mt], bfr[nt][0], bfr[nt][1]);
        }
    }
    __syncthreads();      // all compute done before epilogue overwrites stage smem

    // ---------------- epilogue: all 8 warps tile 128x128 disjointly ----------------
    #pragma unroll
    for (int mt = 0; mt < 2; mt++) {
        int r = wm + mt * 16 + g;
        #pragma unroll
        for (int nt = 0; nt < 8; nt++) {
            int cl = wn + nt * 8 + tg * 2;
            float b0 = smf[SMD_BIAS + cl];
            float b1 = smf[SMD_BIAS + cl + 1];
            float2 v0 = {d[mt][nt][0] + b0, d[mt][nt][1] + b1};
            float2 v1 = {d[mt][nt][2] + b0, d[mt][nt][3] + b1};
            *(float2*)&smf[r * 132 + cl]       = v0;
            *(float2*)&smf[(r + 8) * 132 + cl] = v1;
        }
    }
    __syncthreads();

    if (blockIdx.x < 4) {       // logits region: softmax per 64-col head group
        int r = tid >> 1, hg = tid & 1;
        const float* row = smf + r * 132 + hg * 64;
        float v[64];
        float m = row[0];
        #pragma unroll
        for (int i = 0; i < 64; i++) { v[i] = row[i]; m = fmaxf(m, v[i]); }
        float ssum = 0.f;
        #pragma unroll
        for (int i = 0; i < 64; i++) { v[i] = expf(v[i] - m); ssum += v[i]; }
        float inv = 1.f / ssum;
        __half* op = out + (size_t)(m0 + r) * NTOT + n0 + hg * 64;
        #pragma unroll
        for (int i = 0; i < 64; i += 8) {
            float4 a = {v[i] * inv, v[i+1] * inv, v[i+2] * inv, v[i+3] * inv};
            float4 b = {v[i+4] * inv, v[i+5] * inv, v[i+6] * inv, v[i+7] * inv};
            *(uint4*)(op + i) = pack8(a, b);
        }
    } else {                    // V region: plain fp16 store
        for (int i = tid; i < 128 * 16; i += 256) {
            int r = i >> 4, c8 = (i & 15) * 8;
            float4 a = *(const float4*)&smf[r * 132 + c8];
            float4 b = *(const float4*)&smf[r * 132 + c8 + 4];
            *(uint4*)&out[(size_t)(m0 + r) * NTOT + n0 + c8] = pack8(a, b);
        }
    }
}

// ---------------- 6. tensor-core accum: Num = W^T V, C = colsum(W) ----------------
__device__ __forceinline__ void acc_load(uint32_t wbase, uint32_t vbase,
                                         size_t grow0, int h, int ch, int buf, int tid) {
    #pragma unroll
    for (int l = 0; l < 4; l++) {
        int t = tid + l * 128;
        int r = t >> 3, cc = t & 7;
        size_t ga = (grow0 + (size_t)ch * 64 + r) * NTOT + h * HD + cc * 8;
        uint32_t off = ((uint32_t)buf * 4096 + r * 64 + ((cc ^ (r & 7)) * 8)) * 2;
        asm volatile("cp.async.cg.shared.global [%0], [%1], 16;"
                     :: "r"(wbase + off), "l"(d_LVh + ga));
        asm volatile("cp.async.cg.shared.global [%0], [%1], 16;"
                     :: "r"(vbase + off), "l"(d_LVh + ga + 512));
    }
    asm volatile("cp.async.commit_group;" ::: "memory");
}

__global__ __launch_bounds__(128) void accum_mma() {
    __shared__ __half Wst[2][64 * 64];
    __shared__ __half Vst[2][64 * 64];
    int sc = blockIdx.x, h = blockIdx.y, b = blockIdx.z;
    int tid = threadIdx.x, warp = tid >> 5, lane = tid & 31;
    int q1 = (lane >> 3) & 1, q2 = lane >> 4;
    uint32_t wbase = s2u(Wst), vbase = s2u(Vst);
    size_t grow0 = (size_t)b * SEQ + sc * 1024;

    float acc[8][4];
    #pragma unroll
    for (int nt = 0; nt < 8; nt++)
        #pragma unroll
        for (int i = 0; i < 4; i++) acc[nt][i] = 0.f;
    float cacc0 = 0.f, cacc1 = 0.f;

    acc_load(wbase, vbase, grow0, h, 0, 0, tid);
    for (int ch = 0; ch < 16; ch++) {
        int buf = ch & 1;
        if (ch + 1 < 16) {
            acc_load(wbase, vbase, grow0, h, ch + 1, buf ^ 1, tid);
            asm volatile("cp.async.wait_group 1;" ::: "memory");
        } else {
            asm volatile("cp.async.wait_group 0;" ::: "memory");
        }
        __syncthreads();
        #pragma unroll
        for (int ks = 0; ks < 4; ks++) {
            int s_loc = ks * 16 + q2 * 8 + (lane & 7);
            uint32_t a[4];
            {
                int cc = warp * 2 + q1;
                uint32_t ad = wbase + ((uint32_t)buf * 4096 + s_loc * 64 + ((cc ^ (s_loc & 7)) * 8)) * 2;
                LDSM4T(a[0], a[1], a[2], a[3], ad);
            }
            {   // slot-sum of W from A fragments
                float2 f;
                f = __half22float2(*(__half2*)&a[0]); cacc0 += f.x + f.y;
                f = __half22float2(*(__half2*)&a[2]); cacc0 += f.x + f.y;
                f = __half22float2(*(__half2*)&a[1]); cacc1 += f.x + f.y;
                f = __half22float2(*(__half2*)&a[3]); cacc1 += f.x + f.y;
            }
            #pragma unroll
            for (int p = 0; p < 4; p++) {
                uint32_t r0, r1, r2, r3;
                int cc = p * 2 + q1;
                uint32_t vd = vbase + ((uint32_t)buf * 4096 + s_loc * 64 + ((cc ^ (s_loc & 7)) * 8)) * 2;
                LDSM4T(r0, r1, r2, r3, vd);
                MMA16816(acc[2*p],     a, r0, r2);
                MMA16816(acc[2*p + 1], a, r1, r3);
            }
        }
        __syncthreads();
    }

    cacc0 += __shfl_xor_sync(0xffffffffu, cacc0, 1);
    cacc0 += __shfl_xor_sync(0xffffffffu, cacc0, 2);
    cacc1 += __shfl_xor_sync(0xffffffffu, cacc1, 1);
    cacc1 += __shfl_xor_sync(0xffffffffu, cacc1, 2);
    int slot0 = warp * 16 + (lane >> 2);
    if ((lane & 3) == 0) {
        atomicAdd(&d_C[b * DIM + h * HD + slot0],     cacc0);
        atomicAdd(&d_C[b * DIM + h * HD + slot0 + 8], cacc1);
    }
    #pragma unroll
    for (int nt = 0; nt < 8; nt++) {
        int dc = nt * 8 + (lane & 3) * 2;
        float* p0 = &d_Num[((size_t)b * DIM + h * HD + slot0) * HD + dc];
        float* p1 = &d_Num[((size_t)b * DIM + h * HD + slot0 + 8) * HD + dc];
        atomicAdd(p0,     acc[nt][0]);
        atomicAdd(p0 + 1, acc[nt][1]);
        atomicAdd(p1,     acc[nt][2]);
        atomicAdd(p1 + 1, acc[nt][3]);
    }
}

// ---------------- 7. divide, transpose, final LN ----------------
__global__ void final_kernel(const float* __restrict__ g,
                             const float* __restrict__ bb,
                             float* __restrict__ out) {
    __shared__ float sbuf[32];
    int blk = blockIdx.x;
    int b = blk >> 6, k = blk & 63;
    int tid = threadIdx.x;
    int h = tid >> 6, d = tid & 63;
    float c = d_C[b * DIM + h * HD + k];
    float v = d_Num[((size_t)b * DIM + h * HD + k) * HD + d] / (c + EPS_C);
    float mu = blockReduceSum(v, sbuf) * (1.f / DIM);
    float dv = v - mu;
    float var = blockReduceSum(dv * dv, sbuf) * (1.f / DIM);
    out[(size_t)blk * DIM + tid] = dv * rsqrtf(var + LN_EPS) * g[tid] + bb[tid];
}

// ---------------- launch ----------------
extern "C" void kernel_launch(void* const* d_in, const int* in_sizes, int n_in,
                              void* d_out, int out_size) {
    const float* X       = (const float*)d_in[0];
    const float* slots_w = (const float*)d_in[1];
    const float* g_slots = (const float*)d_in[2];
    const float* b_slots = (const float*)d_in[3];
    const float* Wk      = (const float*)d_in[4];
    const float* bk      = (const float*)d_in[5];
    const float* Wv      = (const float*)d_in[6];
    const float* bv      = (const float*)d_in[7];
    const float* g_after = (const float*)d_in[8];
    const float* b_after = (const float*)d_in[9];
    float* out = (float*)d_out;

    __half *pXh, *pWh, *pLVh;
    float *pbcat;
    cudaGetSymbolAddress((void**)&pXh, d_Xh);
    cudaGetSymbolAddress((void**)&pWh, d_Wh);
    cudaGetSymbolAddress((void**)&pbcat, d_bcat);
    cudaGetSymbolAddress((void**)&pLVh, d_LVh);

    static bool attr_set = false;
    if (!attr_set) {
        cudaFuncSetAttribute(gemm_fp16, cudaFuncAttributeMaxDynamicSharedMemorySize, SMEM_BYTES);
        attr_set = true;
    }

    ln_slots_kernel<<<KSLOTS, DIM>>>(slots_w, g_slots, b_slots);
    fold_kernel<<<DIM, 256>>>(Wk, bk);
    conv_all<<<CONVX_BLKS + CONVW_BLKS + ZERO_BLKS, 256>>>(X, Wv, bv);

    dim3 ggrid(NTOT / NT, BT / MT);   // (8, 512)
    gemm_fp16<<<ggrid, 256, SMEM_BYTES>>>(pXh, pWh, pbcat, pLVh);

    accum_mma<<<dim3(8, HEADS, BATCH), 128>>>();
    final_kernel<<<BATCH * KSLOTS, DIM>>>(g_after, b_after, out);
}